// round 14
// baseline (speedup 1.0000x reference)
#include <cuda_runtime.h>
#include <cuda_fp16.h>
#include <math.h>
#include <stdint.h>

// Problem constants
#define BATCH 2
#define SEQ   2048
#define EMBED 1024
#define HEADS 16
#define HDIM  64
#define MROWS (BATCH * SEQ)   // 4096

// ---------------- scratch (device globals; no runtime allocation) ----------
__device__ __half g_qh[MROWS * EMBED];
__device__ __half g_kh[MROWS * EMBED];
__device__ __half g_vh[MROWS * EMBED];
__device__ __half g_Wqt[EMBED * EMBED];   // transposed: Wt[n][k] = W[k][n]
__device__ __half g_Wkt[EMBED * EMBED];
__device__ __half g_Wvt[EMBED * EMBED];
__device__ __half g_Wot[EMBED * EMBED];
__device__ __half g_Qp[MROWS * EMBED];    // Q projected (pre-scaled)
__device__ __half g_Kp[MROWS * EMBED];
__device__ __half g_Vt[MROWS * EMBED];    // V projected, [bb][h][d][seq]
__device__ __half g_Ah[MROWS * EMBED];    // attention output (fp16)

// ---------------- helpers ---------------------------------------------------
__device__ __forceinline__ float ex2(float x) {
    float r;
    asm("ex2.approx.f32 %0, %1;" : "=f"(r) : "f"(x));
    return r;
}

__device__ __forceinline__ void cp_async16(void* smem_ptr, const void* gmem_ptr) {
    uint32_t s = (uint32_t)__cvta_generic_to_shared(smem_ptr);
    asm volatile("cp.async.cg.shared.global [%0], [%1], 16;\n" :: "r"(s), "l"(gmem_ptr));
}
#define CP_ASYNC_COMMIT() asm volatile("cp.async.commit_group;\n" ::: "memory")
#define CP_ASYNC_WAIT0()  asm volatile("cp.async.wait_group 0;\n" ::: "memory")
#define CP_ASYNC_WAIT1()  asm volatile("cp.async.wait_group 1;\n" ::: "memory")

__device__ __forceinline__ void mma_f16(float& d0, float& d1, float& d2, float& d3,
                                        uint32_t a0, uint32_t a1, uint32_t a2, uint32_t a3,
                                        uint32_t b0, uint32_t b1) {
    asm volatile(
        "mma.sync.aligned.m16n8k16.row.col.f32.f16.f16.f32 "
        "{%0,%1,%2,%3}, {%4,%5,%6,%7}, {%8,%9}, {%0,%1,%2,%3};\n"
        : "+f"(d0), "+f"(d1), "+f"(d2), "+f"(d3)
        : "r"(a0), "r"(a1), "r"(a2), "r"(a3), "r"(b0), "r"(b1));
}

__device__ __forceinline__ void ldsm_x4(uint32_t& r0, uint32_t& r1,
                                        uint32_t& r2, uint32_t& r3, uint32_t addr) {
    asm volatile("ldmatrix.sync.aligned.m8n8.x4.shared.b16 {%0,%1,%2,%3}, [%4];"
                 : "=r"(r0), "=r"(r1), "=r"(r2), "=r"(r3) : "r"(addr));
}

// ---------------- pre-passes -------------------------------------------------
__global__ __launch_bounds__(256)
void cvt_inputs(const float4* __restrict__ q, const float4* __restrict__ k,
                const float4* __restrict__ v,
                __half2* __restrict__ qo, __half2* __restrict__ ko,
                __half2* __restrict__ vo, int n4)
{
    const float4* in  = (blockIdx.y == 0) ? q  : (blockIdx.y == 1) ? k  : v;
    __half2*      out = (blockIdx.y == 0) ? qo : (blockIdx.y == 1) ? ko : vo;
    int i = blockIdx.x * blockDim.x + threadIdx.x;
    if (i < n4) {
        float4 t = in[i];
        out[2 * i]     = __float22half2_rn(make_float2(t.x, t.y));
        out[2 * i + 1] = __float22half2_rn(make_float2(t.z, t.w));
    }
}

__global__ __launch_bounds__(256)
void transpose_h4(const float* __restrict__ W0, const float* __restrict__ W1,
                  const float* __restrict__ W2, const float* __restrict__ W3,
                  __half* __restrict__ T0, __half* __restrict__ T1,
                  __half* __restrict__ T2, __half* __restrict__ T3)
{
    __shared__ float tile[32][33];
    const float* W = (blockIdx.z == 0) ? W0 : (blockIdx.z == 1) ? W1
                   : (blockIdx.z == 2) ? W2 : W3;
    __half* T = (blockIdx.z == 0) ? T0 : (blockIdx.z == 1) ? T1
              : (blockIdx.z == 2) ? T2 : T3;
    const int tx = threadIdx.x;
    const int ty = threadIdx.y;
    const int k0 = blockIdx.x * 32;
    const int n0 = blockIdx.y * 32;
    #pragma unroll
    for (int j = 0; j < 32; j += 8)
        tile[ty + j][tx] = W[(size_t)(k0 + ty + j) * EMBED + n0 + tx];
    __syncthreads();
    #pragma unroll
    for (int j = 0; j < 32; j += 8)
        T[(size_t)(n0 + ty + j) * EMBED + k0 + tx] = __float2half_rn(tile[tx][ty + j]);
}

// ---------------- FP16 tensor-core GEMM: C = A[M,K] @ Bt[N,K]^T + bias ------
// Block tile 128x128, 4 warps (64x64 warp tile), BK=64 (16 iterations),
// double-buffered dynamic SMEM, ldmatrix fragment loads.
#define GBK 64
#define G_STRH 72              // halves per row (128B data + 16B pad)
#define G_ROWB 144
#define G_TILEH (128 * G_STRH)           // one matrix, one stage
#define G_STAGEH (2 * G_TILEH)
#define GEMM_SMEM_BYTES (2 * G_STAGEH * 2)   // 73728 B

template<int MODE>
__global__ __launch_bounds__(128, 2)
void gemm_f16(const __half* __restrict__ A,
              const __half* __restrict__ Bt,
              const float* __restrict__ bias,
              void* __restrict__ Cv,
              float scale)
{
    extern __shared__ __half gsm[];

    const int tid  = threadIdx.x;
    const int wid  = tid >> 5;
    const int lane = tid & 31;
    const int gi   = lane >> 2;
    const int ti   = lane & 3;
    const int mi   = lane >> 3;
    const int lr   = lane & 7;
    const int K    = EMBED;

    const int brow = blockIdx.y;
    const int bcol = blockIdx.x;
    const int warp_m = (wid & 1) * 64;
    const int warp_n = (wid >> 1) * 64;

    const __half* Ablk = A  + (size_t)(brow * 128) * K;
    const __half* Bblk = Bt + (size_t)(bcol * 128) * K;

    const uint32_t smU = (uint32_t)__cvta_generic_to_shared(gsm);
    const uint32_t laneA = (uint32_t)(((mi & 1) * 8 + lr) * G_ROWB + (mi >> 1) * 16);
    const uint32_t laneB = (uint32_t)(((mi >> 1) * 8 + lr) * G_ROWB + (mi & 1) * 16);

    float acc[4][8][4];
    #pragma unroll
    for (int i = 0; i < 4; i++)
        #pragma unroll
        for (int j = 0; j < 8; j++)
            #pragma unroll
            for (int r = 0; r < 4; r++) acc[i][j][r] = 0.0f;

    const int NIT = K / GBK;   // 16

    auto load_tile = [&](int buf, int k0) {
        __half* As = gsm + buf * G_STAGEH;
        __half* Bs = As + G_TILEH;
        #pragma unroll
        for (int i = 0; i < 8; i++) {
            int f = tid + i * 128;     // 0..1023
            int r = f >> 3;            // 0..127
            int c = f & 7;             // 16B chunk 0..7
            cp_async16(&As[r * G_STRH + c * 8], Ablk + (size_t)r * K + k0 + c * 8);
            cp_async16(&Bs[r * G_STRH + c * 8], Bblk + (size_t)r * K + k0 + c * 8);
        }
        CP_ASYNC_COMMIT();
    };

    load_tile(0, 0);

    int buf = 0;
    for (int it = 0; it < NIT; it++) {
        CP_ASYNC_WAIT0();
        __syncthreads();
        if (it + 1 < NIT) load_tile(buf ^ 1, (it + 1) * GBK);

        const uint32_t Au = smU + (uint32_t)buf * (G_STAGEH * 2);
        const uint32_t Bu = Au + (uint32_t)(G_TILEH * 2);
        #pragma unroll
        for (int ks = 0; ks < 4; ks++) {   // four k16 chunks per BK=64
            uint32_t afr[4][4];
            #pragma unroll
            for (int mt = 0; mt < 4; mt++)
                ldsm_x4(afr[mt][0], afr[mt][1], afr[mt][2], afr[mt][3],
                        Au + (uint32_t)((warp_m + mt * 16) * G_ROWB + ks * 32) + laneA);
            uint32_t bfr[8][2];
            #pragma unroll
            for (int p = 0; p < 4; p++)
                ldsm_x4(bfr[2 * p][0], bfr[2 * p][1], bfr[2 * p + 1][0], bfr[2 * p + 1][1],
                        Bu + (uint32_t)((warp_n + p * 16) * G_ROWB + ks * 32) + laneB);
            #pragma unroll
            for (int mt = 0; mt < 4; mt++)
                #pragma unroll
                for (int nt = 0; nt < 8; nt++)
                    mma_f16(acc[mt][nt][0], acc[mt][nt][1],
                            acc[mt][nt][2], acc[mt][nt][3],
                            afr[mt][0], afr[mt][1], afr[mt][2], afr[mt][3],
                            bfr[nt][0], bfr[nt][1]);
        }
        buf ^= 1;
        __syncthreads();
    }

    #pragma unroll
    for (int mt = 0; mt < 4; mt++) {
        int row0 = brow * 128 + warp_m + mt * 16 + gi;
        #pragma unroll
        for (int nt = 0; nt < 8; nt++) {
            int col0 = bcol * 128 + warp_n + nt * 8 + 2 * ti;
            float b0 = bias[col0], b1 = bias[col0 + 1];
            float c00 = (acc[mt][nt][0] + b0) * scale, c01 = (acc[mt][nt][1] + b1) * scale;
            float c10 = (acc[mt][nt][2] + b0) * scale, c11 = (acc[mt][nt][3] + b1) * scale;
            if (MODE == 0) {
                float* C = (float*)Cv;
                *(float2*)(C + (size_t)row0 * EMBED + col0)       = make_float2(c00, c01);
                *(float2*)(C + (size_t)(row0 + 8) * EMBED + col0) = make_float2(c10, c11);
            } else if (MODE == 1) {
                __half* C = (__half*)Cv;
                *(__half2*)(C + (size_t)row0 * EMBED + col0) =
                    __float22half2_rn(make_float2(c00, c01));
                *(__half2*)(C + (size_t)(row0 + 8) * EMBED + col0) =
                    __float22half2_rn(make_float2(c10, c11));
            } else {
                // Vt[((bb*16+h)*64 + d)*2048 + seq]
                __half* C = (__half*)Cv;
                int h  = col0 >> 6;
                int d0 = col0 & 63;
                #pragma unroll
                for (int rr = 0; rr < 2; rr++) {
                    int row = row0 + rr * 8;
                    int bb  = row >> 11, seq = row & 2047;
                    size_t base = ((size_t)((bb * HEADS + h) * HDIM)) * SEQ + seq;
                    C[base + (size_t)d0 * SEQ]       = __float2half_rn(rr ? c10 : c00);
                    C[base + (size_t)(d0 + 1) * SEQ] = __float2half_rn(rr ? c11 : c01);
                }
            }
        }
    }
}

// ---------------- FP16 mma flash attention ----------------------------------
// 4 warps, 32 Q rows/warp. 128-key stages (one cp.async group + one barrier
// per 128 keys), processed as two 64-key subtiles. All operands via ldmatrix.
#define A_STRH  72              // K tile: halves per row (128B + 16B pad)
#define A_ROWB  144
#define V_STRH  136             // V tile: 64 d-rows x 128 keys (256B + 16B pad)
#define V_ROWB  272
#define K_TILEH (128 * A_STRH)             // 128 key rows
#define V_TILEH (64 * V_STRH)              // 64 d rows
#define KV_STAGEH (K_TILEH + V_TILEH)
#define PB_H     (128 * A_STRH)
#define ATTN_SMEM_BYTES ((2 * KV_STAGEH + PB_H) * 2)

__global__ __launch_bounds__(128, 2)
void attn_f16_kernel(const __half* __restrict__ Qp,
                     const __half* __restrict__ Kp,
                     const __half* __restrict__ Vt,
                     __half* __restrict__ Out)
{
    extern __shared__ __half smh[];
    __half* Pb = smh + 2 * KV_STAGEH;

    const int tid  = threadIdx.x;
    const int wid  = tid >> 5;
    const int lane = tid & 31;
    const int gi   = lane >> 2;
    const int ti   = lane & 3;
    const int mi   = lane >> 3;
    const int lr   = lane & 7;
    const int h    = blockIdx.y;
    const int bb   = blockIdx.z;
    const int q0   = blockIdx.x * 128;

    const __half* Qbase  = Qp + ((size_t)(bb * SEQ + q0)) * EMBED + h * HDIM;
    const __half* Kbase  = Kp + ((size_t)bb * SEQ) * EMBED + h * HDIM;
    const __half* Vtbase = Vt + ((size_t)((bb * HEADS + h) * HDIM)) * SEQ;

    const uint32_t smU = (uint32_t)__cvta_generic_to_shared(smh);
    const uint32_t PbU = smU + (uint32_t)(2 * KV_STAGEH * 2);
    const uint32_t PwU = PbU + (uint32_t)((wid * 32) * A_ROWB);
    const uint32_t laneKB = (uint32_t)(lr * A_ROWB + mi * 16);
    const uint32_t laneVB = (uint32_t)(lr * V_ROWB + mi * 16);
    const uint32_t lanePA = (uint32_t)(((mi & 1) * 8 + lr) * A_ROWB + (mi >> 1) * 16);

    // ---- stage Q tile [128 x 64 halves] into Pb ----
    #pragma unroll
    for (int i = 0; i < 8; i++) {
        int f = tid + i * 128;          // 0..1023
        int r = f >> 3, c = f & 7;
        cp_async16(&Pb[r * A_STRH + c * 8], Qbase + (size_t)r * EMBED + c * 8);
    }
    CP_ASYNC_COMMIT();
    CP_ASYNC_WAIT0();
    __syncthreads();

    uint32_t qf[2][4][4];
    #pragma unroll
    for (int mt = 0; mt < 2; mt++)
        #pragma unroll
        for (int ks = 0; ks < 4; ks++)
            ldsm_x4(qf[mt][ks][0], qf[mt][ks][1], qf[mt][ks][2], qf[mt][ks][3],
                    PwU + (uint32_t)(mt * 16 * A_ROWB + ks * 32) + lanePA);
    __syncthreads();   // Pb now free for P

    float oacc[2][8][4];
    #pragma unroll
    for (int mt = 0; mt < 2; mt++)
        #pragma unroll
        for (int nt = 0; nt < 8; nt++)
            #pragma unroll
            for (int r = 0; r < 4; r++) oacc[mt][nt][r] = 0.0f;
    float mA[2] = {-1e30f, -1e30f}, mB[2] = {-1e30f, -1e30f};
    float lA[2] = {0.0f, 0.0f},     lB[2] = {0.0f, 0.0f};

    // stage = K[128 keys][64 d] + V[64 d][128 keys]
    auto load_kv = [&](int t, int s) {
        const __half* Kt = Kbase + (size_t)(t * 128) * EMBED;
        const __half* Vg = Vtbase + t * 128;
        __half* Kd = smh + s * KV_STAGEH;
        __half* Vd = Kd + K_TILEH;
        #pragma unroll
        for (int i = 0; i < 8; i++) {
            int f = tid + i * 128;          // 0..1023
            int rk = f >> 3, ck = f & 7;    // K: 128 rows x 8 chunks
            cp_async16(&Kd[rk * A_STRH + ck * 8], Kt + (size_t)rk * EMBED + ck * 8);
            int rv = f >> 4, cv = f & 15;   // V: 64 rows x 16 chunks
            cp_async16(&Vd[rv * V_STRH + cv * 8], Vg + (size_t)rv * SEQ + cv * 8);
        }
        CP_ASYNC_COMMIT();
    };

    const int NT = SEQ / 128;   // 16
    load_kv(0, 0);
    int buf = 0;

    __half* Pw = Pb + (wid * 32) * A_STRH;

    for (int t = 0; t < NT; t++) {
        if (t + 1 < NT) {
            load_kv(t + 1, buf ^ 1);
            CP_ASYNC_WAIT1();
        } else {
            CP_ASYNC_WAIT0();
        }
        __syncthreads();

        const uint32_t KdU = smU + (uint32_t)(buf * KV_STAGEH * 2);
        const uint32_t VdU = KdU + (uint32_t)(K_TILEH * 2);

        #pragma unroll
        for (int sub = 0; sub < 2; sub++) {
            const uint32_t KsubU = KdU + (uint32_t)(sub * 64 * A_ROWB);
            const uint32_t VsubB = VdU + (uint32_t)(sub * 128);   // key offset: 64*2B

            // ---- S = Q K^T ----
            float sv[2][8][4];
            #pragma unroll
            for (int nt = 0; nt < 8; nt++) {
                uint32_t kb[8];
                uint32_t base = KsubU + (uint32_t)(nt * 8 * A_ROWB) + laneKB;
                ldsm_x4(kb[0], kb[1], kb[2], kb[3], base);
                ldsm_x4(kb[4], kb[5], kb[6], kb[7], base + 64);
                #pragma unroll
                for (int r = 0; r < 4; r++) { sv[0][nt][r] = 0.0f; sv[1][nt][r] = 0.0f; }
                #pragma unroll
                for (int ks = 0; ks < 4; ks++) {
                    mma_f16(sv[0][nt][0], sv[0][nt][1], sv[0][nt][2], sv[0][nt][3],
                            qf[0][ks][0], qf[0][ks][1], qf[0][ks][2], qf[0][ks][3],
                            kb[2 * ks], kb[2 * ks + 1]);
                    mma_f16(sv[1][nt][0], sv[1][nt][1], sv[1][nt][2], sv[1][nt][3],
                            qf[1][ks][0], qf[1][ks][1], qf[1][ks][2], qf[1][ks][3],
                            kb[2 * ks], kb[2 * ks + 1]);
                }
            }

            // ---- online softmax per m-tile (packed f16x2 ex2) ----
            #pragma unroll
            for (int mt = 0; mt < 2; mt++) {
                float mAt = -1e30f, mBt = -1e30f;
                #pragma unroll
                for (int nt = 0; nt < 8; nt++) {
                    mAt = fmaxf(mAt, fmaxf(sv[mt][nt][0], sv[mt][nt][1]));
                    mBt = fmaxf(mBt, fmaxf(sv[mt][nt][2], sv[mt][nt][3]));
                }
                mAt = fmaxf(mAt, __shfl_xor_sync(0xffffffffu, mAt, 1));
                mAt = fmaxf(mAt, __shfl_xor_sync(0xffffffffu, mAt, 2));
                mBt = fmaxf(mBt, __shfl_xor_sync(0xffffffffu, mBt, 1));
                mBt = fmaxf(mBt, __shfl_xor_sync(0xffffffffu, mBt, 2));

                float mA_new = fmaxf(mA[mt], mAt), mB_new = fmaxf(mB[mt], mBt);
                float cA = ex2(mA[mt] - mA_new), cB = ex2(mB[mt] - mB_new);

                const __half2 mh2A = __float2half2_rn(mA_new);
                const __half2 mh2B = __float2half2_rn(mB_new);
                __half2 sumA = __float2half2_rn(0.0f);
                __half2 sumB = __float2half2_rn(0.0f);

                int rlo = mt * 16 + gi, rhi = rlo + 8;
                #pragma unroll
                for (int nt = 0; nt < 8; nt++) {
                    __half2 s01 = __floats2half2_rn(sv[mt][nt][0], sv[mt][nt][1]);
                    __half2 s23 = __floats2half2_rn(sv[mt][nt][2], sv[mt][nt][3]);
                    __half2 pA = h2exp2(__hsub2(s01, mh2A));
                    __half2 pB = h2exp2(__hsub2(s23, mh2B));
                    sumA = __hadd2(sumA, pA);
                    sumB = __hadd2(sumB, pB);
                    *(__half2*)&Pw[rlo * A_STRH + nt * 8 + 2 * ti] = pA;
                    *(__half2*)&Pw[rhi * A_STRH + nt * 8 + 2 * ti] = pB;
                }
                float2 fA = __half22float2(sumA);
                float2 fB = __half22float2(sumB);
                float sA = fA.x + fA.y, sB = fB.x + fB.y;
                sA += __shfl_xor_sync(0xffffffffu, sA, 1);
                sA += __shfl_xor_sync(0xffffffffu, sA, 2);
                sB += __shfl_xor_sync(0xffffffffu, sB, 1);
                sB += __shfl_xor_sync(0xffffffffu, sB, 2);

                lA[mt] = lA[mt] * cA + sA;
                lB[mt] = lB[mt] * cB + sB;
                mA[mt] = mA_new; mB[mt] = mB_new;

                #pragma unroll
                for (int nt = 0; nt < 8; nt++) {
                    oacc[mt][nt][0] *= cA; oacc[mt][nt][1] *= cA;
                    oacc[mt][nt][2] *= cB; oacc[mt][nt][3] *= cB;
                }
            }
            __syncwarp();

            // ---- O += P V ----
            uint32_t pa[2][4][4];
            #pragma unroll
            for (int mt = 0; mt < 2; mt++)
                #pragma unroll
                for (int ks = 0; ks < 4; ks++)
                    ldsm_x4(pa[mt][ks][0], pa[mt][ks][1], pa[mt][ks][2], pa[mt][ks][3],
                            PwU + (uint32_t)(mt * 16 * A_ROWB + ks * 32) + lanePA);

            #pragma unroll
            for (int nt = 0; nt < 8; nt++) {
                uint32_t vb[8];
                uint32_t base = VsubB + (uint32_t)(nt * 8 * V_ROWB) + laneVB;
                ldsm_x4(vb[0], vb[1], vb[2], vb[3], base);
                ldsm_x4(vb[4], vb[5], vb[6], vb[7], base + 64);
                #pragma unroll
                for (int ks = 0; ks < 4; ks++) {
                    mma_f16(oacc[0][nt][0], oacc[0][nt][1], oacc[0][nt][2], oacc[0][nt][3],
                            pa[0][ks][0], pa[0][ks][1], pa[0][ks][2], pa[0][ks][3],
                            vb[2 * ks], vb[2 * ks + 1]);
                    mma_f16(oacc[1][nt][0], oacc[1][nt][1], oacc[1][nt][2], oacc[1][nt][3],
                            pa[1][ks][0], pa[1][ks][1], pa[1][ks][2], pa[1][ks][3],
                            vb[2 * ks], vb[2 * ks + 1]);
                }
            }
            __syncwarp();
        }
        __syncthreads();
        buf ^= 1;
    }

    // ---- epilogue: normalize + fp16 store ----
    #pragma unroll
    for (int mt = 0; mt < 2; mt++) {
        const float invA = 1.0f / lA[mt], invB = 1.0f / lB[mt];
        const int row0 = q0 + wid * 32 + mt * 16 + gi;
        __half* Ob = Out + ((size_t)(bb * SEQ + row0)) * EMBED + h * HDIM;
        #pragma unroll
        for (int nt = 0; nt < 8; nt++) {
            int col = nt * 8 + 2 * ti;
            *(__half2*)(Ob + col) = __float22half2_rn(
                make_float2(oacc[mt][nt][0] * invA, oacc[mt][nt][1] * invA));
            *(__half2*)(Ob + (size_t)8 * EMBED + col) = __float22half2_rn(
                make_float2(oacc[mt][nt][2] * invB, oacc[mt][nt][3] * invB));
        }
    }
}

// ---------------- launch ----------------------------------------------------
extern "C" void kernel_launch(void* const* d_in, const int* in_sizes, int n_in,
                              void* d_out, int out_size)
{
    const float* q  = (const float*)d_in[0];
    const float* k  = (const float*)d_in[1];
    const float* v  = (const float*)d_in[2];
    const float* Wq = (const float*)d_in[3];
    const float* bq = (const float*)d_in[4];
    const float* Wk = (const float*)d_in[5];
    const float* bk = (const float*)d_in[6];
    const float* Wv = (const float*)d_in[7];
    const float* bv = (const float*)d_in[8];
    const float* Wo = (const float*)d_in[9];
    const float* bo = (const float*)d_in[10];
    float* out = (float*)d_out;

    __half *qh, *kh, *vh, *Wqt, *Wkt, *Wvt, *Wot, *Qp, *Kp, *Vt, *Ah;
    cudaGetSymbolAddress((void**)&qh,  g_qh);
    cudaGetSymbolAddress((void**)&kh,  g_kh);
    cudaGetSymbolAddress((void**)&vh,  g_vh);
    cudaGetSymbolAddress((void**)&Wqt, g_Wqt);
    cudaGetSymbolAddress((void**)&Wkt, g_Wkt);
    cudaGetSymbolAddress((void**)&Wvt, g_Wvt);
    cudaGetSymbolAddress((void**)&Wot, g_Wot);
    cudaGetSymbolAddress((void**)&Qp,  g_Qp);
    cudaGetSymbolAddress((void**)&Kp,  g_Kp);
    cudaGetSymbolAddress((void**)&Vt,  g_Vt);
    cudaGetSymbolAddress((void**)&Ah,  g_Ah);

    cudaFuncSetAttribute(gemm_f16<0>,
                         cudaFuncAttributeMaxDynamicSharedMemorySize, GEMM_SMEM_BYTES);
    cudaFuncSetAttribute(gemm_f16<1>,
                         cudaFuncAttributeMaxDynamicSharedMemorySize, GEMM_SMEM_BYTES);
    cudaFuncSetAttribute(gemm_f16<2>,
                         cudaFuncAttributeMaxDynamicSharedMemorySize, GEMM_SMEM_BYTES);
    cudaFuncSetAttribute(attn_f16_kernel,
                         cudaFuncAttributeMaxDynamicSharedMemorySize, ATTN_SMEM_BYTES);

    const int BIG4 = MROWS * EMBED / 4;
    dim3 rgrid(BIG4 / 256, 3);
    cvt_inputs<<<rgrid, 256>>>((const float4*)q, (const float4*)k, (const float4*)v,
                               (__half2*)qh, (__half2*)kh, (__half2*)vh, BIG4);
    dim3 tgrid(EMBED / 32, EMBED / 32, 4);
    dim3 tblk(32, 8);
    transpose_h4<<<tgrid, tblk>>>(Wq, Wk, Wv, Wo, Wqt, Wkt, Wvt, Wot);

    const float qscale = 0.125f * 1.4426950408889634f;   // 1/sqrt(64) * log2(e)
    dim3 gemm_grid(EMBED / 128, MROWS / 128);   // (8, 32)
    gemm_f16<1><<<gemm_grid, 128, GEMM_SMEM_BYTES>>>(qh, Wqt, bq, Qp, qscale);
    gemm_f16<1><<<gemm_grid, 128, GEMM_SMEM_BYTES>>>(kh, Wkt, bk, Kp, 1.0f);
    gemm_f16<2><<<gemm_grid, 128, GEMM_SMEM_BYTES>>>(vh, Wvt, bv, Vt, 1.0f);

    dim3 attn_grid(SEQ / 128, HEADS, BATCH);    // (16, 16, 2)
    attn_f16_kernel<<<attn_grid, 128, ATTN_SMEM_BYTES>>>(Qp, Kp, Vt, Ah);

    gemm_f16<0><<<gemm_grid, 128, GEMM_SMEM_BYTES>>>(Ah, Wot, bo, out, 1.0f);
}

// round 15
// speedup vs baseline: 1.0600x; 1.0600x over previous
#include <cuda_runtime.h>
#include <cuda_fp16.h>
#include <math.h>
#include <stdint.h>

// Problem constants
#define BATCH 2
#define SEQ   2048
#define EMBED 1024
#define HEADS 16
#define HDIM  64
#define MROWS (BATCH * SEQ)   // 4096

// ---------------- scratch (device globals; no runtime allocation) ----------
__device__ __half g_qh[MROWS * EMBED];
__device__ __half g_kh[MROWS * EMBED];
__device__ __half g_vh[MROWS * EMBED];
__device__ __half g_Wqt[EMBED * EMBED];   // transposed: Wt[n][k] = W[k][n]
__device__ __half g_Wkt[EMBED * EMBED];
__device__ __half g_Wvt[EMBED * EMBED];
__device__ __half g_Wot[EMBED * EMBED];
__device__ __half g_Qp[MROWS * EMBED];    // Q projected (pre-scaled)
__device__ __half g_Kp[MROWS * EMBED];
__device__ __half g_Vt[MROWS * EMBED];    // V projected, [bb][h][d][seq]
__device__ __half g_Ah[MROWS * EMBED];    // attention output (fp16)

// ---------------- helpers ---------------------------------------------------
__device__ __forceinline__ float ex2(float x) {
    float r;
    asm("ex2.approx.f32 %0, %1;" : "=f"(r) : "f"(x));
    return r;
}

__device__ __forceinline__ void cp_async16(void* smem_ptr, const void* gmem_ptr) {
    uint32_t s = (uint32_t)__cvta_generic_to_shared(smem_ptr);
    asm volatile("cp.async.cg.shared.global [%0], [%1], 16;\n" :: "r"(s), "l"(gmem_ptr));
}
#define CP_ASYNC_COMMIT() asm volatile("cp.async.commit_group;\n" ::: "memory")
#define CP_ASYNC_WAIT0()  asm volatile("cp.async.wait_group 0;\n" ::: "memory")
#define CP_ASYNC_WAIT1()  asm volatile("cp.async.wait_group 1;\n" ::: "memory")

// fp16 MMA, fp32 accumulate
__device__ __forceinline__ void mma_f16(float& d0, float& d1, float& d2, float& d3,
                                        uint32_t a0, uint32_t a1, uint32_t a2, uint32_t a3,
                                        uint32_t b0, uint32_t b1) {
    asm volatile(
        "mma.sync.aligned.m16n8k16.row.col.f32.f16.f16.f32 "
        "{%0,%1,%2,%3}, {%4,%5,%6,%7}, {%8,%9}, {%0,%1,%2,%3};\n"
        : "+f"(d0), "+f"(d1), "+f"(d2), "+f"(d3)
        : "r"(a0), "r"(a1), "r"(a2), "r"(a3), "r"(b0), "r"(b1));
}

// fp16 MMA, fp16 accumulate: d0 = half2(row gi, cols {2ti,2ti+1}),
// d1 = half2(row gi+8, cols {2ti,2ti+1})
__device__ __forceinline__ void mma_f16acc(uint32_t& d0, uint32_t& d1,
                                           uint32_t a0, uint32_t a1, uint32_t a2, uint32_t a3,
                                           uint32_t b0, uint32_t b1) {
    asm volatile(
        "mma.sync.aligned.m16n8k16.row.col.f16.f16.f16.f16 "
        "{%0,%1}, {%2,%3,%4,%5}, {%6,%7}, {%0,%1};\n"
        : "+r"(d0), "+r"(d1)
        : "r"(a0), "r"(a1), "r"(a2), "r"(a3), "r"(b0), "r"(b1));
}

__device__ __forceinline__ void ldsm_x4(uint32_t& r0, uint32_t& r1,
                                        uint32_t& r2, uint32_t& r3, uint32_t addr) {
    asm volatile("ldmatrix.sync.aligned.m8n8.x4.shared.b16 {%0,%1,%2,%3}, [%4];"
                 : "=r"(r0), "=r"(r1), "=r"(r2), "=r"(r3) : "r"(addr));
}

// ---------------- pre-passes -------------------------------------------------
__global__ __launch_bounds__(256)
void cvt_inputs(const float4* __restrict__ q, const float4* __restrict__ k,
                const float4* __restrict__ v,
                __half2* __restrict__ qo, __half2* __restrict__ ko,
                __half2* __restrict__ vo, int n4)
{
    const float4* in  = (blockIdx.y == 0) ? q  : (blockIdx.y == 1) ? k  : v;
    __half2*      out = (blockIdx.y == 0) ? qo : (blockIdx.y == 1) ? ko : vo;
    int i = blockIdx.x * blockDim.x + threadIdx.x;
    if (i < n4) {
        float4 t = in[i];
        out[2 * i]     = __float22half2_rn(make_float2(t.x, t.y));
        out[2 * i + 1] = __float22half2_rn(make_float2(t.z, t.w));
    }
}

__global__ __launch_bounds__(256)
void transpose_h4(const float* __restrict__ W0, const float* __restrict__ W1,
                  const float* __restrict__ W2, const float* __restrict__ W3,
                  __half* __restrict__ T0, __half* __restrict__ T1,
                  __half* __restrict__ T2, __half* __restrict__ T3)
{
    __shared__ float tile[32][33];
    const float* W = (blockIdx.z == 0) ? W0 : (blockIdx.z == 1) ? W1
                   : (blockIdx.z == 2) ? W2 : W3;
    __half* T = (blockIdx.z == 0) ? T0 : (blockIdx.z == 1) ? T1
              : (blockIdx.z == 2) ? T2 : T3;
    const int tx = threadIdx.x;
    const int ty = threadIdx.y;
    const int k0 = blockIdx.x * 32;
    const int n0 = blockIdx.y * 32;
    #pragma unroll
    for (int j = 0; j < 32; j += 8)
        tile[ty + j][tx] = W[(size_t)(k0 + ty + j) * EMBED + n0 + tx];
    __syncthreads();
    #pragma unroll
    for (int j = 0; j < 32; j += 8)
        T[(size_t)(n0 + ty + j) * EMBED + k0 + tx] = __float2half_rn(tile[tx][ty + j]);
}

// ---------------- FP16 tensor-core GEMM (R12 proven version) ----------------
#define GBK 32
#define G_STRH 40              // halves per tile row (64B data + 16B pad)
#define G_ROWB 80              // bytes
#define G_TILEH (128 * G_STRH)

template<int MODE>
__global__ __launch_bounds__(128, 2)
void gemm_f16(const __half* __restrict__ A,
              const __half* __restrict__ Bt,
              const float* __restrict__ bias,
              void* __restrict__ Cv,
              float scale)
{
    __shared__ __half As[2][G_TILEH];
    __shared__ __half Bs[2][G_TILEH];

    const int tid  = threadIdx.x;
    const int wid  = tid >> 5;
    const int lane = tid & 31;
    const int gi   = lane >> 2;
    const int ti   = lane & 3;
    const int mi   = lane >> 3;
    const int lr   = lane & 7;
    const int K    = EMBED;

    const int brow = blockIdx.y;
    const int bcol = blockIdx.x;
    const int warp_m = (wid & 1) * 64;
    const int warp_n = (wid >> 1) * 64;

    const __half* Ablk = A  + (size_t)(brow * 128) * K;
    const __half* Bblk = Bt + (size_t)(bcol * 128) * K;

    const uint32_t AsU = (uint32_t)__cvta_generic_to_shared(&As[0][0]);
    const uint32_t BsU = (uint32_t)__cvta_generic_to_shared(&Bs[0][0]);
    const uint32_t laneA = (uint32_t)(((mi & 1) * 8 + lr) * G_ROWB + (mi >> 1) * 16);
    const uint32_t laneB = (uint32_t)(((mi >> 1) * 8 + lr) * G_ROWB + (mi & 1) * 16);

    float acc[4][8][4];
    #pragma unroll
    for (int i = 0; i < 4; i++)
        #pragma unroll
        for (int j = 0; j < 8; j++)
            #pragma unroll
            for (int r = 0; r < 4; r++) acc[i][j][r] = 0.0f;

    const int NIT = K / GBK;   // 32

    auto load_tile = [&](int buf, int k0) {
        #pragma unroll
        for (int i = 0; i < 4; i++) {
            int f = tid + i * 128;     // 0..511
            int r = f >> 2;            // 0..127
            int c = f & 3;             // 16B chunk
            cp_async16(&As[buf][r * G_STRH + c * 8], Ablk + (size_t)r * K + k0 + c * 8);
            cp_async16(&Bs[buf][r * G_STRH + c * 8], Bblk + (size_t)r * K + k0 + c * 8);
        }
        CP_ASYNC_COMMIT();
    };

    load_tile(0, 0);

    int buf = 0;
    for (int it = 0; it < NIT; it++) {
        CP_ASYNC_WAIT0();
        __syncthreads();
        if (it + 1 < NIT) load_tile(buf ^ 1, (it + 1) * GBK);

        const uint32_t Au = AsU + (uint32_t)buf * (G_TILEH * 2);
        const uint32_t Bu = BsU + (uint32_t)buf * (G_TILEH * 2);
        #pragma unroll
        for (int ks = 0; ks < 2; ks++) {
            uint32_t afr[4][4];
            #pragma unroll
            for (int mt = 0; mt < 4; mt++)
                ldsm_x4(afr[mt][0], afr[mt][1], afr[mt][2], afr[mt][3],
                        Au + (uint32_t)((warp_m + mt * 16) * G_ROWB + ks * 32) + laneA);
            uint32_t bfr[8][2];
            #pragma unroll
            for (int p = 0; p < 4; p++)
                ldsm_x4(bfr[2 * p][0], bfr[2 * p][1], bfr[2 * p + 1][0], bfr[2 * p + 1][1],
                        Bu + (uint32_t)((warp_n + p * 16) * G_ROWB + ks * 32) + laneB);
            #pragma unroll
            for (int mt = 0; mt < 4; mt++)
                #pragma unroll
                for (int nt = 0; nt < 8; nt++)
                    mma_f16(acc[mt][nt][0], acc[mt][nt][1],
                            acc[mt][nt][2], acc[mt][nt][3],
                            afr[mt][0], afr[mt][1], afr[mt][2], afr[mt][3],
                            bfr[nt][0], bfr[nt][1]);
        }
        buf ^= 1;
        __syncthreads();
    }

    #pragma unroll
    for (int mt = 0; mt < 4; mt++) {
        int row0 = brow * 128 + warp_m + mt * 16 + gi;
        #pragma unroll
        for (int nt = 0; nt < 8; nt++) {
            int col0 = bcol * 128 + warp_n + nt * 8 + 2 * ti;
            float b0 = bias[col0], b1 = bias[col0 + 1];
            float c00 = (acc[mt][nt][0] + b0) * scale, c01 = (acc[mt][nt][1] + b1) * scale;
            float c10 = (acc[mt][nt][2] + b0) * scale, c11 = (acc[mt][nt][3] + b1) * scale;
            if (MODE == 0) {
                float* C = (float*)Cv;
                *(float2*)(C + (size_t)row0 * EMBED + col0)       = make_float2(c00, c01);
                *(float2*)(C + (size_t)(row0 + 8) * EMBED + col0) = make_float2(c10, c11);
            } else if (MODE == 1) {
                __half* C = (__half*)Cv;
                *(__half2*)(C + (size_t)row0 * EMBED + col0) =
                    __float22half2_rn(make_float2(c00, c01));
                *(__half2*)(C + (size_t)(row0 + 8) * EMBED + col0) =
                    __float22half2_rn(make_float2(c10, c11));
            } else {
                // Vt[((bb*16+h)*64 + d)*2048 + seq]
                __half* C = (__half*)Cv;
                int h  = col0 >> 6;
                int d0 = col0 & 63;
                #pragma unroll
                for (int rr = 0; rr < 2; rr++) {
                    int row = row0 + rr * 8;
                    int bb  = row >> 11, seq = row & 2047;
                    size_t base = ((size_t)((bb * HEADS + h) * HDIM)) * SEQ + seq;
                    C[base + (size_t)d0 * SEQ]       = __float2half_rn(rr ? c10 : c00);
                    C[base + (size_t)(d0 + 1) * SEQ] = __float2half_rn(rr ? c11 : c01);
                }
            }
        }
    }
}

// ---------------- FP16 mma flash attention ----------------------------------
// 4 warps, 32 Q rows/warp, 64-key tiles, all operands via ldmatrix.
// QK^T uses fp16 accumulators: S emerges packed as half2 in the P-store
// layout (no cvt), max via hmax2, p via h2exp2. PV keeps fp32 accumulators.
#define A_STRH  72              // halves per row (128B data + 16B pad)
#define A_ROWB  144
#define KS_TILEH (64 * A_STRH)
#define VT_TILEH (64 * A_STRH)
#define PB_H     (128 * A_STRH)
#define ATTN_SMEM_BYTES ((2 * KS_TILEH + 2 * VT_TILEH + PB_H) * 2)

__global__ __launch_bounds__(128, 2)
void attn_f16_kernel(const __half* __restrict__ Qp,
                     const __half* __restrict__ Kp,
                     const __half* __restrict__ Vt,
                     __half* __restrict__ Out)
{
    extern __shared__ __half smh[];
    __half* KsBuf = smh;
    __half* VsBuf = smh + 2 * KS_TILEH;
    __half* Pb    = smh + 2 * KS_TILEH + 2 * VT_TILEH;

    const int tid  = threadIdx.x;
    const int wid  = tid >> 5;
    const int lane = tid & 31;
    const int gi   = lane >> 2;
    const int ti   = lane & 3;
    const int mi   = lane >> 3;
    const int lr   = lane & 7;
    const int h    = blockIdx.y;
    const int bb   = blockIdx.z;
    const int q0   = blockIdx.x * 128;

    const __half* Qbase  = Qp + ((size_t)(bb * SEQ + q0)) * EMBED + h * HDIM;
    const __half* Kbase  = Kp + ((size_t)bb * SEQ) * EMBED + h * HDIM;
    const __half* Vtbase = Vt + ((size_t)((bb * HEADS + h) * HDIM)) * SEQ;

    const uint32_t KsU = (uint32_t)__cvta_generic_to_shared(KsBuf);
    const uint32_t VsU = (uint32_t)__cvta_generic_to_shared(VsBuf);
    const uint32_t PbU = (uint32_t)__cvta_generic_to_shared(Pb);
    const uint32_t PwU = PbU + (uint32_t)((wid * 32) * A_ROWB);
    const uint32_t laneKB = (uint32_t)(lr * A_ROWB + mi * 16);
    const uint32_t lanePA = (uint32_t)(((mi & 1) * 8 + lr) * A_ROWB + (mi >> 1) * 16);

    // ---- stage Q tile [128 x 64 halves] into Pb ----
    #pragma unroll
    for (int i = 0; i < 8; i++) {
        int f = tid + i * 128;          // 0..1023
        int r = f >> 3, c = f & 7;
        cp_async16(&Pb[r * A_STRH + c * 8], Qbase + (size_t)r * EMBED + c * 8);
    }
    CP_ASYNC_COMMIT();
    CP_ASYNC_WAIT0();
    __syncthreads();

    uint32_t qf[2][4][4];
    #pragma unroll
    for (int mt = 0; mt < 2; mt++)
        #pragma unroll
        for (int ks = 0; ks < 4; ks++)
            ldsm_x4(qf[mt][ks][0], qf[mt][ks][1], qf[mt][ks][2], qf[mt][ks][3],
                    PwU + (uint32_t)(mt * 16 * A_ROWB + ks * 32) + lanePA);
    __syncthreads();   // Pb now free for P

    float oacc[2][8][4];
    #pragma unroll
    for (int mt = 0; mt < 2; mt++)
        #pragma unroll
        for (int nt = 0; nt < 8; nt++)
            #pragma unroll
            for (int r = 0; r < 4; r++) oacc[mt][nt][r] = 0.0f;
    float mA[2] = {-1e30f, -1e30f}, mB[2] = {-1e30f, -1e30f};
    float lA[2] = {0.0f, 0.0f},     lB[2] = {0.0f, 0.0f};

    auto load_kv = [&](int t, int s) {
        const __half* Kt = Kbase + (size_t)(t * 64) * EMBED;
        const __half* Vg = Vtbase + t * 64;
        __half* Kd = KsBuf + s * KS_TILEH;
        __half* Vd = VsBuf + s * VT_TILEH;
        #pragma unroll
        for (int i = 0; i < 4; i++) {
            int f = tid + i * 128;      // 0..511
            int r = f >> 3, c = f & 7;
            cp_async16(&Kd[r * A_STRH + c * 8], Kt + (size_t)r * EMBED + c * 8);
            cp_async16(&Vd[r * A_STRH + c * 8], Vg + (size_t)r * SEQ + c * 8);
        }
        CP_ASYNC_COMMIT();
    };

    const int NT = SEQ / 64;   // 32
    load_kv(0, 0);
    int buf = 0;

    __half* Pw = Pb + (wid * 32) * A_STRH;

    for (int t = 0; t < NT; t++) {
        if (t + 1 < NT) {
            load_kv(t + 1, buf ^ 1);
            CP_ASYNC_WAIT1();
        } else {
            CP_ASYNC_WAIT0();
        }
        __syncthreads();

        const uint32_t KdU = KsU + (uint32_t)(buf * KS_TILEH * 2);
        const uint32_t VdU = VsU + (uint32_t)(buf * VT_TILEH * 2);

        // ---- S = Q K^T with fp16 accumulators (packed half2 outputs) ----
        // sA2[mt][nt] = half2 S(row mt*16+gi,    cols nt*8+2ti, +1)
        // sB2[mt][nt] = half2 S(row mt*16+gi+8,  cols nt*8+2ti, +1)
        uint32_t sA2[2][8], sB2[2][8];
        #pragma unroll
        for (int nt = 0; nt < 8; nt++) {
            uint32_t kb[8];
            uint32_t base = KdU + (uint32_t)(nt * 8 * A_ROWB) + laneKB;
            ldsm_x4(kb[0], kb[1], kb[2], kb[3], base);
            ldsm_x4(kb[4], kb[5], kb[6], kb[7], base + 64);
            sA2[0][nt] = 0u; sB2[0][nt] = 0u;
            sA2[1][nt] = 0u; sB2[1][nt] = 0u;
            #pragma unroll
            for (int ks = 0; ks < 4; ks++) {
                mma_f16acc(sA2[0][nt], sB2[0][nt],
                           qf[0][ks][0], qf[0][ks][1], qf[0][ks][2], qf[0][ks][3],
                           kb[2 * ks], kb[2 * ks + 1]);
                mma_f16acc(sA2[1][nt], sB2[1][nt],
                           qf[1][ks][0], qf[1][ks][1], qf[1][ks][2], qf[1][ks][3],
                           kb[2 * ks], kb[2 * ks + 1]);
            }
        }

        // ---- online softmax per m-tile (all-f16 data path) ----
        #pragma unroll
        for (int mt = 0; mt < 2; mt++) {
            __half2 mxA = *(__half2*)&sA2[mt][0];
            __half2 mxB = *(__half2*)&sB2[mt][0];
            #pragma unroll
            for (int nt = 1; nt < 8; nt++) {
                mxA = __hmax2(mxA, *(__half2*)&sA2[mt][nt]);
                mxB = __hmax2(mxB, *(__half2*)&sB2[mt][nt]);
            }
            float mAt = fmaxf(__low2float(mxA), __high2float(mxA));
            float mBt = fmaxf(__low2float(mxB), __high2float(mxB));
            mAt = fmaxf(mAt, __shfl_xor_sync(0xffffffffu, mAt, 1));
            mAt = fmaxf(mAt, __shfl_xor_sync(0xffffffffu, mAt, 2));
            mBt = fmaxf(mBt, __shfl_xor_sync(0xffffffffu, mBt, 1));
            mBt = fmaxf(mBt, __shfl_xor_sync(0xffffffffu, mBt, 2));

            float mA_new = fmaxf(mA[mt], mAt), mB_new = fmaxf(mB[mt], mBt);
            float cA = ex2(mA[mt] - mA_new), cB = ex2(mB[mt] - mB_new);

            const __half2 mh2A = __float2half2_rn(mA_new);
            const __half2 mh2B = __float2half2_rn(mB_new);
            __half2 sumA = __float2half2_rn(0.0f);
            __half2 sumB = __float2half2_rn(0.0f);

            int rlo = mt * 16 + gi, rhi = rlo + 8;
            #pragma unroll
            for (int nt = 0; nt < 8; nt++) {
                __half2 pA = h2exp2(__hsub2(*(__half2*)&sA2[mt][nt], mh2A));
                __half2 pB = h2exp2(__hsub2(*(__half2*)&sB2[mt][nt], mh2B));
                sumA = __hadd2(sumA, pA);
                sumB = __hadd2(sumB, pB);
                *(__half2*)&Pw[rlo * A_STRH + nt * 8 + 2 * ti] = pA;
                *(__half2*)&Pw[rhi * A_STRH + nt * 8 + 2 * ti] = pB;
            }
            float2 fA = __half22float2(sumA);
            float2 fB = __half22float2(sumB);
            float sA = fA.x + fA.y, sB = fB.x + fB.y;
            sA += __shfl_xor_sync(0xffffffffu, sA, 1);
            sA += __shfl_xor_sync(0xffffffffu, sA, 2);
            sB += __shfl_xor_sync(0xffffffffu, sB, 1);
            sB += __shfl_xor_sync(0xffffffffu, sB, 2);

            lA[mt] = lA[mt] * cA + sA;
            lB[mt] = lB[mt] * cB + sB;
            mA[mt] = mA_new; mB[mt] = mB_new;

            #pragma unroll
            for (int nt = 0; nt < 8; nt++) {
                oacc[mt][nt][0] *= cA; oacc[mt][nt][1] *= cA;
                oacc[mt][nt][2] *= cB; oacc[mt][nt][3] *= cB;
            }
        }
        __syncwarp();

        // ---- O += P V : pa hoisted (8 LDSM), vb (16 LDSM), fp32 acc ----
        uint32_t pa[2][4][4];
        #pragma unroll
        for (int mt = 0; mt < 2; mt++)
            #pragma unroll
            for (int ks = 0; ks < 4; ks++)
                ldsm_x4(pa[mt][ks][0], pa[mt][ks][1], pa[mt][ks][2], pa[mt][ks][3],
                        PwU + (uint32_t)(mt * 16 * A_ROWB + ks * 32) + lanePA);

        #pragma unroll
        for (int nt = 0; nt < 8; nt++) {
            uint32_t vb[8];
            uint32_t base = VdU + (uint32_t)(nt * 8 * A_ROWB) + laneKB;
            ldsm_x4(vb[0], vb[1], vb[2], vb[3], base);
            ldsm_x4(vb[4], vb[5], vb[6], vb[7], base + 64);
            #pragma unroll
            for (int ks = 0; ks < 4; ks++) {
                mma_f16(oacc[0][nt][0], oacc[0][nt][1], oacc[0][nt][2], oacc[0][nt][3],
                        pa[0][ks][0], pa[0][ks][1], pa[0][ks][2], pa[0][ks][3],
                        vb[2 * ks], vb[2 * ks + 1]);
                mma_f16(oacc[1][nt][0], oacc[1][nt][1], oacc[1][nt][2], oacc[1][nt][3],
                        pa[1][ks][0], pa[1][ks][1], pa[1][ks][2], pa[1][ks][3],
                        vb[2 * ks], vb[2 * ks + 1]);
            }
        }
        __syncthreads();
        buf ^= 1;
    }

    // ---- epilogue: normalize + fp16 store ----
    #pragma unroll
    for (int mt = 0; mt < 2; mt++) {
        const float invA = 1.0f / lA[mt], invB = 1.0f / lB[mt];
        const int row0 = q0 + wid * 32 + mt * 16 + gi;
        __half* Ob = Out + ((size_t)(bb * SEQ + row0)) * EMBED + h * HDIM;
        #pragma unroll
        for (int nt = 0; nt < 8; nt++) {
            int col = nt * 8 + 2 * ti;
            *(__half2*)(Ob + col) = __float22half2_rn(
                make_float2(oacc[mt][nt][0] * invA, oacc[mt][nt][1] * invA));
            *(__half2*)(Ob + (size_t)8 * EMBED + col) = __float22half2_rn(
                make_float2(oacc[mt][nt][2] * invB, oacc[mt][nt][3] * invB));
        }
    }
}

// ---------------- launch ----------------------------------------------------
extern "C" void kernel_launch(void* const* d_in, const int* in_sizes, int n_in,
                              void* d_out, int out_size)
{
    const float* q  = (const float*)d_in[0];
    const float* k  = (const float*)d_in[1];
    const float* v  = (const float*)d_in[2];
    const float* Wq = (const float*)d_in[3];
    const float* bq = (const float*)d_in[4];
    const float* Wk = (const float*)d_in[5];
    const float* bk = (const float*)d_in[6];
    const float* Wv = (const float*)d_in[7];
    const float* bv = (const float*)d_in[8];
    const float* Wo = (const float*)d_in[9];
    const float* bo = (const float*)d_in[10];
    float* out = (float*)d_out;

    __half *qh, *kh, *vh, *Wqt, *Wkt, *Wvt, *Wot, *Qp, *Kp, *Vt, *Ah;
    cudaGetSymbolAddress((void**)&qh,  g_qh);
    cudaGetSymbolAddress((void**)&kh,  g_kh);
    cudaGetSymbolAddress((void**)&vh,  g_vh);
    cudaGetSymbolAddress((void**)&Wqt, g_Wqt);
    cudaGetSymbolAddress((void**)&Wkt, g_Wkt);
    cudaGetSymbolAddress((void**)&Wvt, g_Wvt);
    cudaGetSymbolAddress((void**)&Wot, g_Wot);
    cudaGetSymbolAddress((void**)&Qp,  g_Qp);
    cudaGetSymbolAddress((void**)&Kp,  g_Kp);
    cudaGetSymbolAddress((void**)&Vt,  g_Vt);
    cudaGetSymbolAddress((void**)&Ah,  g_Ah);

    cudaFuncSetAttribute(attn_f16_kernel,
                         cudaFuncAttributeMaxDynamicSharedMemorySize,
                         ATTN_SMEM_BYTES);

    const int BIG4 = MROWS * EMBED / 4;
    dim3 rgrid(BIG4 / 256, 3);
    cvt_inputs<<<rgrid, 256>>>((const float4*)q, (const float4*)k, (const float4*)v,
                               (__half2*)qh, (__half2*)kh, (__half2*)vh, BIG4);
    dim3 tgrid(EMBED / 32, EMBED / 32, 4);
    dim3 tblk(32, 8);
    transpose_h4<<<tgrid, tblk>>>(Wq, Wk, Wv, Wo, Wqt, Wkt, Wvt, Wot);

    const float qscale = 0.125f * 1.4426950408889634f;   // 1/sqrt(64) * log2(e)
    dim3 gemm_grid(EMBED / 128, MROWS / 128);   // (8, 32)
    gemm_f16<1><<<gemm_grid, 128>>>(qh, Wqt, bq, Qp, qscale);
    gemm_f16<1><<<gemm_grid, 128>>>(kh, Wkt, bk, Kp, 1.0f);
    gemm_f16<2><<<gemm_grid, 128>>>(vh, Wvt, bv, Vt, 1.0f);

    dim3 attn_grid(SEQ / 128, HEADS, BATCH);    // (16, 16, 2)
    attn_f16_kernel<<<attn_grid, 128, ATTN_SMEM_BYTES>>>(Qp, Kp, Vt, Ah);

    gemm_f16<0><<<gemm_grid, 128>>>(Ah, Wot, bo, out, 1.0f);
}

// round 16
// speedup vs baseline: 1.0841x; 1.0227x over previous
#include <cuda_runtime.h>
#include <cuda_fp16.h>
#include <math.h>
#include <stdint.h>

// Problem constants
#define BATCH 2
#define SEQ   2048
#define EMBED 1024
#define HEADS 16
#define HDIM  64
#define MROWS (BATCH * SEQ)   // 4096

// ---------------- scratch (device globals; no runtime allocation) ----------
__device__ __half g_qh[MROWS * EMBED];
__device__ __half g_kh[MROWS * EMBED];
__device__ __half g_vh[MROWS * EMBED];
__device__ __half g_Wqt[EMBED * EMBED];   // transposed: Wt[n][k] = W[k][n]
__device__ __half g_Wkt[EMBED * EMBED];
__device__ __half g_Wvt[EMBED * EMBED];
__device__ __half g_Wot[EMBED * EMBED];
__device__ __half g_Qp[MROWS * EMBED];    // Q projected (pre-scaled)
__device__ __half g_Kp[MROWS * EMBED];
__device__ __half g_Vt[MROWS * EMBED];    // V projected, [bb][h][d][seq]
__device__ __half g_Ah[MROWS * EMBED];    // attention output (fp16)

// ---------------- helpers ---------------------------------------------------
__device__ __forceinline__ float ex2(float x) {
    float r;
    asm("ex2.approx.f32 %0, %1;" : "=f"(r) : "f"(x));
    return r;
}

__device__ __forceinline__ void cp_async16(void* smem_ptr, const void* gmem_ptr) {
    uint32_t s = (uint32_t)__cvta_generic_to_shared(smem_ptr);
    asm volatile("cp.async.cg.shared.global [%0], [%1], 16;\n" :: "r"(s), "l"(gmem_ptr));
}
#define CP_ASYNC_COMMIT() asm volatile("cp.async.commit_group;\n" ::: "memory")
#define CP_ASYNC_WAIT0()  asm volatile("cp.async.wait_group 0;\n" ::: "memory")
#define CP_ASYNC_WAIT1()  asm volatile("cp.async.wait_group 1;\n" ::: "memory")

// fp16 MMA, fp32 accumulate
__device__ __forceinline__ void mma_f16(float& d0, float& d1, float& d2, float& d3,
                                        uint32_t a0, uint32_t a1, uint32_t a2, uint32_t a3,
                                        uint32_t b0, uint32_t b1) {
    asm volatile(
        "mma.sync.aligned.m16n8k16.row.col.f32.f16.f16.f32 "
        "{%0,%1,%2,%3}, {%4,%5,%6,%7}, {%8,%9}, {%0,%1,%2,%3};\n"
        : "+f"(d0), "+f"(d1), "+f"(d2), "+f"(d3)
        : "r"(a0), "r"(a1), "r"(a2), "r"(a3), "r"(b0), "r"(b1));
}

// fp16 MMA, fp16 accumulate: d0 = half2(row gi, cols {2ti,2ti+1}),
// d1 = half2(row gi+8, cols {2ti,2ti+1})
__device__ __forceinline__ void mma_f16acc(uint32_t& d0, uint32_t& d1,
                                           uint32_t a0, uint32_t a1, uint32_t a2, uint32_t a3,
                                           uint32_t b0, uint32_t b1) {
    asm volatile(
        "mma.sync.aligned.m16n8k16.row.col.f16.f16.f16.f16 "
        "{%0,%1}, {%2,%3,%4,%5}, {%6,%7}, {%0,%1};\n"
        : "+r"(d0), "+r"(d1)
        : "r"(a0), "r"(a1), "r"(a2), "r"(a3), "r"(b0), "r"(b1));
}

__device__ __forceinline__ void ldsm_x4(uint32_t& r0, uint32_t& r1,
                                        uint32_t& r2, uint32_t& r3, uint32_t addr) {
    asm volatile("ldmatrix.sync.aligned.m8n8.x4.shared.b16 {%0,%1,%2,%3}, [%4];"
                 : "=r"(r0), "=r"(r1), "=r"(r2), "=r"(r3) : "r"(addr));
}

// ---------------- pre-passes -------------------------------------------------
__global__ __launch_bounds__(256)
void cvt_inputs(const float4* __restrict__ q, const float4* __restrict__ k,
                const float4* __restrict__ v,
                __half2* __restrict__ qo, __half2* __restrict__ ko,
                __half2* __restrict__ vo, int n4)
{
    const float4* in  = (blockIdx.y == 0) ? q  : (blockIdx.y == 1) ? k  : v;
    __half2*      out = (blockIdx.y == 0) ? qo : (blockIdx.y == 1) ? ko : vo;
    int i = blockIdx.x * blockDim.x + threadIdx.x;
    if (i < n4) {
        float4 t = in[i];
        out[2 * i]     = __float22half2_rn(make_float2(t.x, t.y));
        out[2 * i + 1] = __float22half2_rn(make_float2(t.z, t.w));
    }
}

__global__ __launch_bounds__(256)
void transpose_h4(const float* __restrict__ W0, const float* __restrict__ W1,
                  const float* __restrict__ W2, const float* __restrict__ W3,
                  __half* __restrict__ T0, __half* __restrict__ T1,
                  __half* __restrict__ T2, __half* __restrict__ T3)
{
    __shared__ float tile[32][33];
    const float* W = (blockIdx.z == 0) ? W0 : (blockIdx.z == 1) ? W1
                   : (blockIdx.z == 2) ? W2 : W3;
    __half* T = (blockIdx.z == 0) ? T0 : (blockIdx.z == 1) ? T1
              : (blockIdx.z == 2) ? T2 : T3;
    const int tx = threadIdx.x;
    const int ty = threadIdx.y;
    const int k0 = blockIdx.x * 32;
    const int n0 = blockIdx.y * 32;
    #pragma unroll
    for (int j = 0; j < 32; j += 8)
        tile[ty + j][tx] = W[(size_t)(k0 + ty + j) * EMBED + n0 + tx];
    __syncthreads();
    #pragma unroll
    for (int j = 0; j < 32; j += 8)
        T[(size_t)(n0 + ty + j) * EMBED + k0 + tx] = __float2half_rn(tile[tx][ty + j]);
}

// ---------------- FP16 tensor-core GEMM (R12 proven version) ----------------
#define GBK 32
#define G_STRH 40              // halves per tile row (64B data + 16B pad)
#define G_ROWB 80              // bytes
#define G_TILEH (128 * G_STRH)

template<int MODE>
__global__ __launch_bounds__(128, 2)
void gemm_f16(const __half* __restrict__ A,
              const __half* __restrict__ Bt,
              const float* __restrict__ bias,
              void* __restrict__ Cv,
              float scale)
{
    __shared__ __half As[2][G_TILEH];
    __shared__ __half Bs[2][G_TILEH];

    const int tid  = threadIdx.x;
    const int wid  = tid >> 5;
    const int lane = tid & 31;
    const int gi   = lane >> 2;
    const int ti   = lane & 3;
    const int mi   = lane >> 3;
    const int lr   = lane & 7;
    const int K    = EMBED;

    const int brow = blockIdx.y;
    const int bcol = blockIdx.x;
    const int warp_m = (wid & 1) * 64;
    const int warp_n = (wid >> 1) * 64;

    const __half* Ablk = A  + (size_t)(brow * 128) * K;
    const __half* Bblk = Bt + (size_t)(bcol * 128) * K;

    const uint32_t AsU = (uint32_t)__cvta_generic_to_shared(&As[0][0]);
    const uint32_t BsU = (uint32_t)__cvta_generic_to_shared(&Bs[0][0]);
    const uint32_t laneA = (uint32_t)(((mi & 1) * 8 + lr) * G_ROWB + (mi >> 1) * 16);
    const uint32_t laneB = (uint32_t)(((mi >> 1) * 8 + lr) * G_ROWB + (mi & 1) * 16);

    float acc[4][8][4];
    #pragma unroll
    for (int i = 0; i < 4; i++)
        #pragma unroll
        for (int j = 0; j < 8; j++)
            #pragma unroll
            for (int r = 0; r < 4; r++) acc[i][j][r] = 0.0f;

    const int NIT = K / GBK;   // 32

    auto load_tile = [&](int buf, int k0) {
        #pragma unroll
        for (int i = 0; i < 4; i++) {
            int f = tid + i * 128;     // 0..511
            int r = f >> 2;            // 0..127
            int c = f & 3;             // 16B chunk
            cp_async16(&As[buf][r * G_STRH + c * 8], Ablk + (size_t)r * K + k0 + c * 8);
            cp_async16(&Bs[buf][r * G_STRH + c * 8], Bblk + (size_t)r * K + k0 + c * 8);
        }
        CP_ASYNC_COMMIT();
    };

    load_tile(0, 0);

    int buf = 0;
    for (int it = 0; it < NIT; it++) {
        CP_ASYNC_WAIT0();
        __syncthreads();
        if (it + 1 < NIT) load_tile(buf ^ 1, (it + 1) * GBK);

        const uint32_t Au = AsU + (uint32_t)buf * (G_TILEH * 2);
        const uint32_t Bu = BsU + (uint32_t)buf * (G_TILEH * 2);
        #pragma unroll
        for (int ks = 0; ks < 2; ks++) {
            uint32_t afr[4][4];
            #pragma unroll
            for (int mt = 0; mt < 4; mt++)
                ldsm_x4(afr[mt][0], afr[mt][1], afr[mt][2], afr[mt][3],
                        Au + (uint32_t)((warp_m + mt * 16) * G_ROWB + ks * 32) + laneA);
            uint32_t bfr[8][2];
            #pragma unroll
            for (int p = 0; p < 4; p++)
                ldsm_x4(bfr[2 * p][0], bfr[2 * p][1], bfr[2 * p + 1][0], bfr[2 * p + 1][1],
                        Bu + (uint32_t)((warp_n + p * 16) * G_ROWB + ks * 32) + laneB);
            #pragma unroll
            for (int mt = 0; mt < 4; mt++)
                #pragma unroll
                for (int nt = 0; nt < 8; nt++)
                    mma_f16(acc[mt][nt][0], acc[mt][nt][1],
                            acc[mt][nt][2], acc[mt][nt][3],
                            afr[mt][0], afr[mt][1], afr[mt][2], afr[mt][3],
                            bfr[nt][0], bfr[nt][1]);
        }
        buf ^= 1;
        __syncthreads();
    }

    #pragma unroll
    for (int mt = 0; mt < 4; mt++) {
        int row0 = brow * 128 + warp_m + mt * 16 + gi;
        #pragma unroll
        for (int nt = 0; nt < 8; nt++) {
            int col0 = bcol * 128 + warp_n + nt * 8 + 2 * ti;
            float b0 = bias[col0], b1 = bias[col0 + 1];
            float c00 = (acc[mt][nt][0] + b0) * scale, c01 = (acc[mt][nt][1] + b1) * scale;
            float c10 = (acc[mt][nt][2] + b0) * scale, c11 = (acc[mt][nt][3] + b1) * scale;
            if (MODE == 0) {
                float* C = (float*)Cv;
                *(float2*)(C + (size_t)row0 * EMBED + col0)       = make_float2(c00, c01);
                *(float2*)(C + (size_t)(row0 + 8) * EMBED + col0) = make_float2(c10, c11);
            } else if (MODE == 1) {
                __half* C = (__half*)Cv;
                *(__half2*)(C + (size_t)row0 * EMBED + col0) =
                    __float22half2_rn(make_float2(c00, c01));
                *(__half2*)(C + (size_t)(row0 + 8) * EMBED + col0) =
                    __float22half2_rn(make_float2(c10, c11));
            } else {
                // Vt[((bb*16+h)*64 + d)*2048 + seq]
                __half* C = (__half*)Cv;
                int h  = col0 >> 6;
                int d0 = col0 & 63;
                #pragma unroll
                for (int rr = 0; rr < 2; rr++) {
                    int row = row0 + rr * 8;
                    int bb  = row >> 11, seq = row & 2047;
                    size_t base = ((size_t)((bb * HEADS + h) * HDIM)) * SEQ + seq;
                    C[base + (size_t)d0 * SEQ]       = __float2half_rn(rr ? c10 : c00);
                    C[base + (size_t)(d0 + 1) * SEQ] = __float2half_rn(rr ? c11 : c01);
                }
            }
        }
    }
}

// ---------------- FP16 mma flash attention ----------------------------------
// 4 warps, 32 Q rows/warp, 64-key tiles. QK^T with fp16 accumulators;
// P = h2exp2(S - m) stays in REGISTERS and is consumed directly as the PV
// a-fragments (c-frag == a-frag layout identity). No P SMEM round-trip.
#define A_STRH  72              // halves per row (128B data + 16B pad)
#define A_ROWB  144
#define KS_TILEH (64 * A_STRH)
#define VT_TILEH (64 * A_STRH)
#define ATTN_SMEM_BYTES ((2 * KS_TILEH + 2 * VT_TILEH) * 2)

__global__ __launch_bounds__(128, 2)
void attn_f16_kernel(const __half* __restrict__ Qp,
                     const __half* __restrict__ Kp,
                     const __half* __restrict__ Vt,
                     __half* __restrict__ Out)
{
    extern __shared__ __half smh[];
    __half* KsBuf = smh;                       // 2 x KS_TILEH (contiguous = 128 rows)
    __half* VsBuf = smh + 2 * KS_TILEH;

    const int tid  = threadIdx.x;
    const int wid  = tid >> 5;
    const int lane = tid & 31;
    const int gi   = lane >> 2;
    const int ti   = lane & 3;
    const int mi   = lane >> 3;
    const int lr   = lane & 7;
    const int h    = blockIdx.y;
    const int bb   = blockIdx.z;
    const int q0   = blockIdx.x * 128;

    const __half* Qbase  = Qp + ((size_t)(bb * SEQ + q0)) * EMBED + h * HDIM;
    const __half* Kbase  = Kp + ((size_t)bb * SEQ) * EMBED + h * HDIM;
    const __half* Vtbase = Vt + ((size_t)((bb * HEADS + h) * HDIM)) * SEQ;

    const uint32_t smU = (uint32_t)__cvta_generic_to_shared(smh);
    const uint32_t VsU = smU + (uint32_t)(2 * KS_TILEH * 2);
    const uint32_t laneKB = (uint32_t)(lr * A_ROWB + mi * 16);
    const uint32_t lanePA = (uint32_t)(((mi & 1) * 8 + lr) * A_ROWB + (mi >> 1) * 16);

    // ---- stage Q [128 x 64 halves] into the contiguous K-stage region ----
    #pragma unroll
    for (int i = 0; i < 8; i++) {
        int f = tid + i * 128;          // 0..1023
        int r = f >> 3, c = f & 7;
        cp_async16(&KsBuf[r * A_STRH + c * 8], Qbase + (size_t)r * EMBED + c * 8);
    }
    CP_ASYNC_COMMIT();
    CP_ASYNC_WAIT0();
    __syncthreads();

    // Q a-frags for this warp's 32 rows (rows wid*32 .. wid*32+31)
    uint32_t qf[2][4][4];
    {
        const uint32_t QwU = smU + (uint32_t)((wid * 32) * A_ROWB);
        #pragma unroll
        for (int mt = 0; mt < 2; mt++)
            #pragma unroll
            for (int ks = 0; ks < 4; ks++)
                ldsm_x4(qf[mt][ks][0], qf[mt][ks][1], qf[mt][ks][2], qf[mt][ks][3],
                        QwU + (uint32_t)(mt * 16 * A_ROWB + ks * 32) + lanePA);
    }
    __syncthreads();   // K-stage region now free for the KV pipeline

    float oacc[2][8][4];
    #pragma unroll
    for (int mt = 0; mt < 2; mt++)
        #pragma unroll
        for (int nt = 0; nt < 8; nt++)
            #pragma unroll
            for (int r = 0; r < 4; r++) oacc[mt][nt][r] = 0.0f;
    float mA[2] = {-1e30f, -1e30f}, mB[2] = {-1e30f, -1e30f};
    float lA[2] = {0.0f, 0.0f},     lB[2] = {0.0f, 0.0f};

    auto load_kv = [&](int t, int s) {
        const __half* Kt = Kbase + (size_t)(t * 64) * EMBED;
        const __half* Vg = Vtbase + t * 64;
        __half* Kd = KsBuf + s * KS_TILEH;
        __half* Vd = VsBuf + s * VT_TILEH;
        #pragma unroll
        for (int i = 0; i < 4; i++) {
            int f = tid + i * 128;      // 0..511
            int r = f >> 3, c = f & 7;
            cp_async16(&Kd[r * A_STRH + c * 8], Kt + (size_t)r * EMBED + c * 8);
            cp_async16(&Vd[r * A_STRH + c * 8], Vg + (size_t)r * SEQ + c * 8);
        }
        CP_ASYNC_COMMIT();
    };

    const int NT = SEQ / 64;   // 32
    load_kv(0, 0);
    int buf = 0;

    for (int t = 0; t < NT; t++) {
        if (t + 1 < NT) {
            load_kv(t + 1, buf ^ 1);
            CP_ASYNC_WAIT1();
        } else {
            CP_ASYNC_WAIT0();
        }
        __syncthreads();

        const uint32_t KdU = smU + (uint32_t)(buf * KS_TILEH * 2);
        const uint32_t VdU = VsU + (uint32_t)(buf * VT_TILEH * 2);

        // ---- S = Q K^T with fp16 accumulators (packed half2 outputs) ----
        uint32_t sA2[2][8], sB2[2][8];
        #pragma unroll
        for (int nt = 0; nt < 8; nt++) {
            uint32_t kb[8];
            uint32_t base = KdU + (uint32_t)(nt * 8 * A_ROWB) + laneKB;
            ldsm_x4(kb[0], kb[1], kb[2], kb[3], base);
            ldsm_x4(kb[4], kb[5], kb[6], kb[7], base + 64);
            sA2[0][nt] = 0u; sB2[0][nt] = 0u;
            sA2[1][nt] = 0u; sB2[1][nt] = 0u;
            #pragma unroll
            for (int ks = 0; ks < 4; ks++) {
                mma_f16acc(sA2[0][nt], sB2[0][nt],
                           qf[0][ks][0], qf[0][ks][1], qf[0][ks][2], qf[0][ks][3],
                           kb[2 * ks], kb[2 * ks + 1]);
                mma_f16acc(sA2[1][nt], sB2[1][nt],
                           qf[1][ks][0], qf[1][ks][1], qf[1][ks][2], qf[1][ks][3],
                           kb[2 * ks], kb[2 * ks + 1]);
            }
        }

        // ---- online softmax; P stays in registers (sA2/sB2 -> p values) ----
        #pragma unroll
        for (int mt = 0; mt < 2; mt++) {
            __half2 mxA = *(__half2*)&sA2[mt][0];
            __half2 mxB = *(__half2*)&sB2[mt][0];
            #pragma unroll
            for (int nt = 1; nt < 8; nt++) {
                mxA = __hmax2(mxA, *(__half2*)&sA2[mt][nt]);
                mxB = __hmax2(mxB, *(__half2*)&sB2[mt][nt]);
            }
            float mAt = fmaxf(__low2float(mxA), __high2float(mxA));
            float mBt = fmaxf(__low2float(mxB), __high2float(mxB));
            mAt = fmaxf(mAt, __shfl_xor_sync(0xffffffffu, mAt, 1));
            mAt = fmaxf(mAt, __shfl_xor_sync(0xffffffffu, mAt, 2));
            mBt = fmaxf(mBt, __shfl_xor_sync(0xffffffffu, mBt, 1));
            mBt = fmaxf(mBt, __shfl_xor_sync(0xffffffffu, mBt, 2));

            float mA_new = fmaxf(mA[mt], mAt), mB_new = fmaxf(mB[mt], mBt);
            float cA = ex2(mA[mt] - mA_new), cB = ex2(mB[mt] - mB_new);

            const __half2 mh2A = __float2half2_rn(mA_new);
            const __half2 mh2B = __float2half2_rn(mB_new);
            __half2 sumA = __float2half2_rn(0.0f);
            __half2 sumB = __float2half2_rn(0.0f);

            #pragma unroll
            for (int nt = 0; nt < 8; nt++) {
                __half2 pA = h2exp2(__hsub2(*(__half2*)&sA2[mt][nt], mh2A));
                __half2 pB = h2exp2(__hsub2(*(__half2*)&sB2[mt][nt], mh2B));
                sumA = __hadd2(sumA, pA);
                sumB = __hadd2(sumB, pB);
                *(__half2*)&sA2[mt][nt] = pA;   // in-place: S -> P
                *(__half2*)&sB2[mt][nt] = pB;
            }
            float2 fA = __half22float2(sumA);
            float2 fB = __half22float2(sumB);
            float sA = fA.x + fA.y, sB = fB.x + fB.y;
            sA += __shfl_xor_sync(0xffffffffu, sA, 1);
            sA += __shfl_xor_sync(0xffffffffu, sA, 2);
            sB += __shfl_xor_sync(0xffffffffu, sB, 1);
            sB += __shfl_xor_sync(0xffffffffu, sB, 2);

            lA[mt] = lA[mt] * cA + sA;
            lB[mt] = lB[mt] * cB + sB;
            mA[mt] = mA_new; mB[mt] = mB_new;

            #pragma unroll
            for (int nt = 0; nt < 8; nt++) {
                oacc[mt][nt][0] *= cA; oacc[mt][nt][1] *= cA;
                oacc[mt][nt][2] *= cB; oacc[mt][nt][3] *= cB;
            }
        }

        // ---- O += P V : P a-frags come straight from registers ----
        // a-frag for k-chunk ks: {pA[2ks], pB[2ks], pA[2ks+1], pB[2ks+1]}
        #pragma unroll
        for (int nt = 0; nt < 8; nt++) {
            uint32_t vb[8];
            uint32_t base = VdU + (uint32_t)(nt * 8 * A_ROWB) + laneKB;
            ldsm_x4(vb[0], vb[1], vb[2], vb[3], base);
            ldsm_x4(vb[4], vb[5], vb[6], vb[7], base + 64);
            #pragma unroll
            for (int ks = 0; ks < 4; ks++) {
                mma_f16(oacc[0][nt][0], oacc[0][nt][1], oacc[0][nt][2], oacc[0][nt][3],
                        sA2[0][2 * ks], sB2[0][2 * ks],
                        sA2[0][2 * ks + 1], sB2[0][2 * ks + 1],
                        vb[2 * ks], vb[2 * ks + 1]);
                mma_f16(oacc[1][nt][0], oacc[1][nt][1], oacc[1][nt][2], oacc[1][nt][3],
                        sA2[1][2 * ks], sB2[1][2 * ks],
                        sA2[1][2 * ks + 1], sB2[1][2 * ks + 1],
                        vb[2 * ks], vb[2 * ks + 1]);
            }
        }
        __syncthreads();
        buf ^= 1;
    }

    // ---- epilogue: normalize + fp16 store ----
    #pragma unroll
    for (int mt = 0; mt < 2; mt++) {
        const float invA = 1.0f / lA[mt], invB = 1.0f / lB[mt];
        const int row0 = q0 + wid * 32 + mt * 16 + gi;
        __half* Ob = Out + ((size_t)(bb * SEQ + row0)) * EMBED + h * HDIM;
        #pragma unroll
        for (int nt = 0; nt < 8; nt++) {
            int col = nt * 8 + 2 * ti;
            *(__half2*)(Ob + col) = __float22half2_rn(
                make_float2(oacc[mt][nt][0] * invA, oacc[mt][nt][1] * invA));
            *(__half2*)(Ob + (size_t)8 * EMBED + col) = __float22half2_rn(
                make_float2(oacc[mt][nt][2] * invB, oacc[mt][nt][3] * invB));
        }
    }
}

// ---------------- launch ----------------------------------------------------
extern "C" void kernel_launch(void* const* d_in, const int* in_sizes, int n_in,
                              void* d_out, int out_size)
{
    const float* q  = (const float*)d_in[0];
    const float* k  = (const float*)d_in[1];
    const float* v  = (const float*)d_in[2];
    const float* Wq = (const float*)d_in[3];
    const float* bq = (const float*)d_in[4];
    const float* Wk = (const float*)d_in[5];
    const float* bk = (const float*)d_in[6];
    const float* Wv = (const float*)d_in[7];
    const float* bv = (const float*)d_in[8];
    const float* Wo = (const float*)d_in[9];
    const float* bo = (const float*)d_in[10];
    float* out = (float*)d_out;

    __half *qh, *kh, *vh, *Wqt, *Wkt, *Wvt, *Wot, *Qp, *Kp, *Vt, *Ah;
    cudaGetSymbolAddress((void**)&qh,  g_qh);
    cudaGetSymbolAddress((void**)&kh,  g_kh);
    cudaGetSymbolAddress((void**)&vh,  g_vh);
    cudaGetSymbolAddress((void**)&Wqt, g_Wqt);
    cudaGetSymbolAddress((void**)&Wkt, g_Wkt);
    cudaGetSymbolAddress((void**)&Wvt, g_Wvt);
    cudaGetSymbolAddress((void**)&Wot, g_Wot);
    cudaGetSymbolAddress((void**)&Qp,  g_Qp);
    cudaGetSymbolAddress((void**)&Kp,  g_Kp);
    cudaGetSymbolAddress((void**)&Vt,  g_Vt);
    cudaGetSymbolAddress((void**)&Ah,  g_Ah);

    cudaFuncSetAttribute(attn_f16_kernel,
                         cudaFuncAttributeMaxDynamicSharedMemorySize,
                         ATTN_SMEM_BYTES);

    const int BIG4 = MROWS * EMBED / 4;
    dim3 rgrid(BIG4 / 256, 3);
    cvt_inputs<<<rgrid, 256>>>((const float4*)q, (const float4*)k, (const float4*)v,
                               (__half2*)qh, (__half2*)kh, (__half2*)vh, BIG4);
    dim3 tgrid(EMBED / 32, EMBED / 32, 4);
    dim3 tblk(32, 8);
    transpose_h4<<<tgrid, tblk>>>(Wq, Wk, Wv, Wo, Wqt, Wkt, Wvt, Wot);

    const float qscale = 0.125f * 1.4426950408889634f;   // 1/sqrt(64) * log2(e)
    dim3 gemm_grid(EMBED / 128, MROWS / 128);   // (8, 32)
    gemm_f16<1><<<gemm_grid, 128>>>(qh, Wqt, bq, Qp, qscale);
    gemm_f16<1><<<gemm_grid, 128>>>(kh, Wkt, bk, Kp, 1.0f);
    gemm_f16<2><<<gemm_grid, 128>>>(vh, Wvt, bv, Vt, 1.0f);

    dim3 attn_grid(SEQ / 128, HEADS, BATCH);    // (16, 16, 2)
    attn_f16_kernel<<<attn_grid, 128, ATTN_SMEM_BYTES>>>(Qp, Kp, Vt, Ah);

    gemm_f16<0><<<gemm_grid, 128>>>(Ah, Wot, bo, out, 1.0f);
}

// round 17
// speedup vs baseline: 1.0935x; 1.0087x over previous
#include <cuda_runtime.h>
#include <cuda_fp16.h>
#include <math.h>
#include <stdint.h>

// Problem constants
#define BATCH 2
#define SEQ   2048
#define EMBED 1024
#define HEADS 16
#define HDIM  64
#define MROWS (BATCH * SEQ)   // 4096

// ---------------- scratch (device globals; no runtime allocation) ----------
__device__ __half g_qh[MROWS * EMBED];
__device__ __half g_kh[MROWS * EMBED];
__device__ __half g_vh[MROWS * EMBED];
__device__ __half g_Wqt[EMBED * EMBED];   // transposed: Wt[n][k] = W[k][n]
__device__ __half g_Wkt[EMBED * EMBED];
__device__ __half g_Wvt[EMBED * EMBED];
__device__ __half g_Wot[EMBED * EMBED];
__device__ __half g_Qp[MROWS * EMBED];    // Q projected (pre-scaled)
__device__ __half g_Kp[MROWS * EMBED];
__device__ __half g_Vt[MROWS * EMBED];    // V projected, [bb][h][d][seq]
__device__ __half g_Ah[MROWS * EMBED];    // attention output (fp16)

// ---------------- helpers ---------------------------------------------------
__device__ __forceinline__ float ex2(float x) {
    float r;
    asm("ex2.approx.f32 %0, %1;" : "=f"(r) : "f"(x));
    return r;
}

__device__ __forceinline__ void cp_async16(void* smem_ptr, const void* gmem_ptr) {
    uint32_t s = (uint32_t)__cvta_generic_to_shared(smem_ptr);
    asm volatile("cp.async.cg.shared.global [%0], [%1], 16;\n" :: "r"(s), "l"(gmem_ptr));
}
#define CP_ASYNC_COMMIT() asm volatile("cp.async.commit_group;\n" ::: "memory")
#define CP_ASYNC_WAIT0()  asm volatile("cp.async.wait_group 0;\n" ::: "memory")
#define CP_ASYNC_WAIT1()  asm volatile("cp.async.wait_group 1;\n" ::: "memory")

// fp16 MMA, fp32 accumulate
__device__ __forceinline__ void mma_f16(float& d0, float& d1, float& d2, float& d3,
                                        uint32_t a0, uint32_t a1, uint32_t a2, uint32_t a3,
                                        uint32_t b0, uint32_t b1) {
    asm volatile(
        "mma.sync.aligned.m16n8k16.row.col.f32.f16.f16.f32 "
        "{%0,%1,%2,%3}, {%4,%5,%6,%7}, {%8,%9}, {%0,%1,%2,%3};\n"
        : "+f"(d0), "+f"(d1), "+f"(d2), "+f"(d3)
        : "r"(a0), "r"(a1), "r"(a2), "r"(a3), "r"(b0), "r"(b1));
}

// fp16 MMA, fp16 accumulate
__device__ __forceinline__ void mma_f16acc(uint32_t& d0, uint32_t& d1,
                                           uint32_t a0, uint32_t a1, uint32_t a2, uint32_t a3,
                                           uint32_t b0, uint32_t b1) {
    asm volatile(
        "mma.sync.aligned.m16n8k16.row.col.f16.f16.f16.f16 "
        "{%0,%1}, {%2,%3,%4,%5}, {%6,%7}, {%0,%1};\n"
        : "+r"(d0), "+r"(d1)
        : "r"(a0), "r"(a1), "r"(a2), "r"(a3), "r"(b0), "r"(b1));
}

__device__ __forceinline__ void ldsm_x4(uint32_t& r0, uint32_t& r1,
                                        uint32_t& r2, uint32_t& r3, uint32_t addr) {
    asm volatile("ldmatrix.sync.aligned.m8n8.x4.shared.b16 {%0,%1,%2,%3}, [%4];"
                 : "=r"(r0), "=r"(r1), "=r"(r2), "=r"(r3) : "r"(addr));
}

// ---------------- unified pre-pass -------------------------------------------
// grid = (4096, 4); y = 0..2: convert q/k/v fp32->fp16 (4096 blocks x 256 f4).
// y = 3: transpose+convert the 4 weight matrices (x encodes wsel | 32x32 tile).
__global__ __launch_bounds__(256)
void prep_kernel(const float4* __restrict__ q, const float4* __restrict__ k,
                 const float4* __restrict__ v,
                 __half2* __restrict__ qo, __half2* __restrict__ ko,
                 __half2* __restrict__ vo,
                 const float* __restrict__ W0, const float* __restrict__ W1,
                 const float* __restrict__ W2, const float* __restrict__ W3,
                 __half* __restrict__ T0, __half* __restrict__ T1,
                 __half* __restrict__ T2, __half* __restrict__ T3)
{
    __shared__ float tile[32][33];
    const int tid = threadIdx.x;
    if (blockIdx.y < 3) {
        const float4* in  = (blockIdx.y == 0) ? q  : (blockIdx.y == 1) ? k  : v;
        __half2*      out = (blockIdx.y == 0) ? qo : (blockIdx.y == 1) ? ko : vo;
        int i = blockIdx.x * 256 + tid;
        float4 t = in[i];
        out[2 * i]     = __float22half2_rn(make_float2(t.x, t.y));
        out[2 * i + 1] = __float22half2_rn(make_float2(t.z, t.w));
    } else {
        const int wsel = blockIdx.x >> 10;          // 0..3
        const int rem  = blockIdx.x & 1023;
        const float* W = (wsel == 0) ? W0 : (wsel == 1) ? W1 : (wsel == 2) ? W2 : W3;
        __half* T = (wsel == 0) ? T0 : (wsel == 1) ? T1 : (wsel == 2) ? T2 : T3;
        const int k0 = (rem & 31) * 32;
        const int n0 = (rem >> 5) * 32;
        const int tx = tid & 31;
        const int ty = tid >> 5;                    // 0..7
        #pragma unroll
        for (int j = 0; j < 32; j += 8)
            tile[ty + j][tx] = W[(size_t)(k0 + ty + j) * EMBED + n0 + tx];
        __syncthreads();
        #pragma unroll
        for (int j = 0; j < 32; j += 8)
            T[(size_t)(n0 + ty + j) * EMBED + k0 + tx] =
                __float2half_rn(tile[tx][ty + j]);
    }
}

// ---------------- FP16 GEMM (job-based; R12 proven body) --------------------
// mode: 0 = fp32 store; 1 = fp16 store; 2 = fp16 store transposed-per-head.
struct GemmJob {
    const __half* A;
    const __half* Bt;
    const float*  bias;
    void*         C;
    float         scale;
    int           mode;
};

#define GBK 32
#define G_STRH 40              // halves per tile row (64B data + 16B pad)
#define G_ROWB 80              // bytes
#define G_TILEH (128 * G_STRH)

__global__ __launch_bounds__(128, 2)
void gemm_f16j(GemmJob j0, GemmJob j1, GemmJob j2)
{
    const GemmJob jb = (blockIdx.z == 0) ? j0 : (blockIdx.z == 1) ? j1 : j2;

    __shared__ __half As[2][G_TILEH];
    __shared__ __half Bs[2][G_TILEH];

    const int tid  = threadIdx.x;
    const int wid  = tid >> 5;
    const int lane = tid & 31;
    const int gi   = lane >> 2;
    const int ti   = lane & 3;
    const int mi   = lane >> 3;
    const int lr   = lane & 7;
    const int K    = EMBED;

    const int brow = blockIdx.y;
    const int bcol = blockIdx.x;
    const int warp_m = (wid & 1) * 64;
    const int warp_n = (wid >> 1) * 64;

    const __half* Ablk = jb.A  + (size_t)(brow * 128) * K;
    const __half* Bblk = jb.Bt + (size_t)(bcol * 128) * K;

    const uint32_t AsU = (uint32_t)__cvta_generic_to_shared(&As[0][0]);
    const uint32_t BsU = (uint32_t)__cvta_generic_to_shared(&Bs[0][0]);
    const uint32_t laneA = (uint32_t)(((mi & 1) * 8 + lr) * G_ROWB + (mi >> 1) * 16);
    const uint32_t laneB = (uint32_t)(((mi >> 1) * 8 + lr) * G_ROWB + (mi & 1) * 16);

    float acc[4][8][4];
    #pragma unroll
    for (int i = 0; i < 4; i++)
        #pragma unroll
        for (int j = 0; j < 8; j++)
            #pragma unroll
            for (int r = 0; r < 4; r++) acc[i][j][r] = 0.0f;

    const int NIT = K / GBK;   // 32

    auto load_tile = [&](int buf, int k0) {
        #pragma unroll
        for (int i = 0; i < 4; i++) {
            int f = tid + i * 128;     // 0..511
            int r = f >> 2;            // 0..127
            int c = f & 3;             // 16B chunk
            cp_async16(&As[buf][r * G_STRH + c * 8], Ablk + (size_t)r * K + k0 + c * 8);
            cp_async16(&Bs[buf][r * G_STRH + c * 8], Bblk + (size_t)r * K + k0 + c * 8);
        }
        CP_ASYNC_COMMIT();
    };

    load_tile(0, 0);

    int buf = 0;
    for (int it = 0; it < NIT; it++) {
        CP_ASYNC_WAIT0();
        __syncthreads();
        if (it + 1 < NIT) load_tile(buf ^ 1, (it + 1) * GBK);

        const uint32_t Au = AsU + (uint32_t)buf * (G_TILEH * 2);
        const uint32_t Bu = BsU + (uint32_t)buf * (G_TILEH * 2);
        #pragma unroll
        for (int ks = 0; ks < 2; ks++) {
            uint32_t afr[4][4];
            #pragma unroll
            for (int mt = 0; mt < 4; mt++)
                ldsm_x4(afr[mt][0], afr[mt][1], afr[mt][2], afr[mt][3],
                        Au + (uint32_t)((warp_m + mt * 16) * G_ROWB + ks * 32) + laneA);
            uint32_t bfr[8][2];
            #pragma unroll
            for (int p = 0; p < 4; p++)
                ldsm_x4(bfr[2 * p][0], bfr[2 * p][1], bfr[2 * p + 1][0], bfr[2 * p + 1][1],
                        Bu + (uint32_t)((warp_n + p * 16) * G_ROWB + ks * 32) + laneB);
            #pragma unroll
            for (int mt = 0; mt < 4; mt++)
                #pragma unroll
                for (int nt = 0; nt < 8; nt++)
                    mma_f16(acc[mt][nt][0], acc[mt][nt][1],
                            acc[mt][nt][2], acc[mt][nt][3],
                            afr[mt][0], afr[mt][1], afr[mt][2], afr[mt][3],
                            bfr[nt][0], bfr[nt][1]);
        }
        buf ^= 1;
        __syncthreads();
    }

    #pragma unroll
    for (int mt = 0; mt < 4; mt++) {
        int row0 = brow * 128 + warp_m + mt * 16 + gi;
        #pragma unroll
        for (int nt = 0; nt < 8; nt++) {
            int col0 = bcol * 128 + warp_n + nt * 8 + 2 * ti;
            float b0 = jb.bias[col0], b1 = jb.bias[col0 + 1];
            float c00 = (acc[mt][nt][0] + b0) * jb.scale;
            float c01 = (acc[mt][nt][1] + b1) * jb.scale;
            float c10 = (acc[mt][nt][2] + b0) * jb.scale;
            float c11 = (acc[mt][nt][3] + b1) * jb.scale;
            if (jb.mode == 0) {
                float* C = (float*)jb.C;
                *(float2*)(C + (size_t)row0 * EMBED + col0)       = make_float2(c00, c01);
                *(float2*)(C + (size_t)(row0 + 8) * EMBED + col0) = make_float2(c10, c11);
            } else if (jb.mode == 1) {
                __half* C = (__half*)jb.C;
                *(__half2*)(C + (size_t)row0 * EMBED + col0) =
                    __float22half2_rn(make_float2(c00, c01));
                *(__half2*)(C + (size_t)(row0 + 8) * EMBED + col0) =
                    __float22half2_rn(make_float2(c10, c11));
            } else {
                // Vt[((bb*16+h)*64 + d)*2048 + seq]
                __half* C = (__half*)jb.C;
                int h  = col0 >> 6;
                int d0 = col0 & 63;
                #pragma unroll
                for (int rr = 0; rr < 2; rr++) {
                    int row = row0 + rr * 8;
                    int bb  = row >> 11, seq = row & 2047;
                    size_t base = ((size_t)((bb * HEADS + h) * HDIM)) * SEQ + seq;
                    C[base + (size_t)d0 * SEQ]       = __float2half_rn(rr ? c10 : c00);
                    C[base + (size_t)(d0 + 1) * SEQ] = __float2half_rn(rr ? c11 : c01);
                }
            }
        }
    }
}

// ---------------- FP16 mma flash attention (R16, unchanged) -----------------
#define A_STRH  72              // halves per row (128B data + 16B pad)
#define A_ROWB  144
#define KS_TILEH (64 * A_STRH)
#define VT_TILEH (64 * A_STRH)
#define ATTN_SMEM_BYTES ((2 * KS_TILEH + 2 * VT_TILEH) * 2)

__global__ __launch_bounds__(128, 2)
void attn_f16_kernel(const __half* __restrict__ Qp,
                     const __half* __restrict__ Kp,
                     const __half* __restrict__ Vt,
                     __half* __restrict__ Out)
{
    extern __shared__ __half smh[];
    __half* KsBuf = smh;
    __half* VsBuf = smh + 2 * KS_TILEH;

    const int tid  = threadIdx.x;
    const int wid  = tid >> 5;
    const int lane = tid & 31;
    const int gi   = lane >> 2;
    const int ti   = lane & 3;
    const int mi   = lane >> 3;
    const int lr   = lane & 7;
    const int h    = blockIdx.y;
    const int bb   = blockIdx.z;
    const int q0   = blockIdx.x * 128;

    const __half* Qbase  = Qp + ((size_t)(bb * SEQ + q0)) * EMBED + h * HDIM;
    const __half* Kbase  = Kp + ((size_t)bb * SEQ) * EMBED + h * HDIM;
    const __half* Vtbase = Vt + ((size_t)((bb * HEADS + h) * HDIM)) * SEQ;

    const uint32_t smU = (uint32_t)__cvta_generic_to_shared(smh);
    const uint32_t VsU = smU + (uint32_t)(2 * KS_TILEH * 2);
    const uint32_t laneKB = (uint32_t)(lr * A_ROWB + mi * 16);
    const uint32_t lanePA = (uint32_t)(((mi & 1) * 8 + lr) * A_ROWB + (mi >> 1) * 16);

    // ---- stage Q [128 x 64 halves] into the contiguous K-stage region ----
    #pragma unroll
    for (int i = 0; i < 8; i++) {
        int f = tid + i * 128;
        int r = f >> 3, c = f & 7;
        cp_async16(&KsBuf[r * A_STRH + c * 8], Qbase + (size_t)r * EMBED + c * 8);
    }
    CP_ASYNC_COMMIT();
    CP_ASYNC_WAIT0();
    __syncthreads();

    uint32_t qf[2][4][4];
    {
        const uint32_t QwU = smU + (uint32_t)((wid * 32) * A_ROWB);
        #pragma unroll
        for (int mt = 0; mt < 2; mt++)
            #pragma unroll
            for (int ks = 0; ks < 4; ks++)
                ldsm_x4(qf[mt][ks][0], qf[mt][ks][1], qf[mt][ks][2], qf[mt][ks][3],
                        QwU + (uint32_t)(mt * 16 * A_ROWB + ks * 32) + lanePA);
    }
    __syncthreads();

    float oacc[2][8][4];
    #pragma unroll
    for (int mt = 0; mt < 2; mt++)
        #pragma unroll
        for (int nt = 0; nt < 8; nt++)
            #pragma unroll
            for (int r = 0; r < 4; r++) oacc[mt][nt][r] = 0.0f;
    float mA[2] = {-1e30f, -1e30f}, mB[2] = {-1e30f, -1e30f};
    float lA[2] = {0.0f, 0.0f},     lB[2] = {0.0f, 0.0f};

    auto load_kv = [&](int t, int s) {
        const __half* Kt = Kbase + (size_t)(t * 64) * EMBED;
        const __half* Vg = Vtbase + t * 64;
        __half* Kd = KsBuf + s * KS_TILEH;
        __half* Vd = VsBuf + s * VT_TILEH;
        #pragma unroll
        for (int i = 0; i < 4; i++) {
            int f = tid + i * 128;
            int r = f >> 3, c = f & 7;
            cp_async16(&Kd[r * A_STRH + c * 8], Kt + (size_t)r * EMBED + c * 8);
            cp_async16(&Vd[r * A_STRH + c * 8], Vg + (size_t)r * SEQ + c * 8);
        }
        CP_ASYNC_COMMIT();
    };

    const int NT = SEQ / 64;   // 32
    load_kv(0, 0);
    int buf = 0;

    for (int t = 0; t < NT; t++) {
        if (t + 1 < NT) {
            load_kv(t + 1, buf ^ 1);
            CP_ASYNC_WAIT1();
        } else {
            CP_ASYNC_WAIT0();
        }
        __syncthreads();

        const uint32_t KdU = smU + (uint32_t)(buf * KS_TILEH * 2);
        const uint32_t VdU = VsU + (uint32_t)(buf * VT_TILEH * 2);

        // ---- S = Q K^T with fp16 accumulators ----
        uint32_t sA2[2][8], sB2[2][8];
        #pragma unroll
        for (int nt = 0; nt < 8; nt++) {
            uint32_t kb[8];
            uint32_t base = KdU + (uint32_t)(nt * 8 * A_ROWB) + laneKB;
            ldsm_x4(kb[0], kb[1], kb[2], kb[3], base);
            ldsm_x4(kb[4], kb[5], kb[6], kb[7], base + 64);
            sA2[0][nt] = 0u; sB2[0][nt] = 0u;
            sA2[1][nt] = 0u; sB2[1][nt] = 0u;
            #pragma unroll
            for (int ks = 0; ks < 4; ks++) {
                mma_f16acc(sA2[0][nt], sB2[0][nt],
                           qf[0][ks][0], qf[0][ks][1], qf[0][ks][2], qf[0][ks][3],
                           kb[2 * ks], kb[2 * ks + 1]);
                mma_f16acc(sA2[1][nt], sB2[1][nt],
                           qf[1][ks][0], qf[1][ks][1], qf[1][ks][2], qf[1][ks][3],
                           kb[2 * ks], kb[2 * ks + 1]);
            }
        }

        // ---- online softmax; P stays in registers ----
        #pragma unroll
        for (int mt = 0; mt < 2; mt++) {
            __half2 mxA = *(__half2*)&sA2[mt][0];
            __half2 mxB = *(__half2*)&sB2[mt][0];
            #pragma unroll
            for (int nt = 1; nt < 8; nt++) {
                mxA = __hmax2(mxA, *(__half2*)&sA2[mt][nt]);
                mxB = __hmax2(mxB, *(__half2*)&sB2[mt][nt]);
            }
            float mAt = fmaxf(__low2float(mxA), __high2float(mxA));
            float mBt = fmaxf(__low2float(mxB), __high2float(mxB));
            mAt = fmaxf(mAt, __shfl_xor_sync(0xffffffffu, mAt, 1));
            mAt = fmaxf(mAt, __shfl_xor_sync(0xffffffffu, mAt, 2));
            mBt = fmaxf(mBt, __shfl_xor_sync(0xffffffffu, mBt, 1));
            mBt = fmaxf(mBt, __shfl_xor_sync(0xffffffffu, mBt, 2));

            float mA_new = fmaxf(mA[mt], mAt), mB_new = fmaxf(mB[mt], mBt);
            float cA = ex2(mA[mt] - mA_new), cB = ex2(mB[mt] - mB_new);

            const __half2 mh2A = __float2half2_rn(mA_new);
            const __half2 mh2B = __float2half2_rn(mB_new);
            __half2 sumA = __float2half2_rn(0.0f);
            __half2 sumB = __float2half2_rn(0.0f);

            #pragma unroll
            for (int nt = 0; nt < 8; nt++) {
                __half2 pA = h2exp2(__hsub2(*(__half2*)&sA2[mt][nt], mh2A));
                __half2 pB = h2exp2(__hsub2(*(__half2*)&sB2[mt][nt], mh2B));
                sumA = __hadd2(sumA, pA);
                sumB = __hadd2(sumB, pB);
                *(__half2*)&sA2[mt][nt] = pA;
                *(__half2*)&sB2[mt][nt] = pB;
            }
            float2 fA = __half22float2(sumA);
            float2 fB = __half22float2(sumB);
            float sA = fA.x + fA.y, sB = fB.x + fB.y;
            sA += __shfl_xor_sync(0xffffffffu, sA, 1);
            sA += __shfl_xor_sync(0xffffffffu, sA, 2);
            sB += __shfl_xor_sync(0xffffffffu, sB, 1);
            sB += __shfl_xor_sync(0xffffffffu, sB, 2);

            lA[mt] = lA[mt] * cA + sA;
            lB[mt] = lB[mt] * cB + sB;
            mA[mt] = mA_new; mB[mt] = mB_new;

            #pragma unroll
            for (int nt = 0; nt < 8; nt++) {
                oacc[mt][nt][0] *= cA; oacc[mt][nt][1] *= cA;
                oacc[mt][nt][2] *= cB; oacc[mt][nt][3] *= cB;
            }
        }

        // ---- O += P V : P a-frags straight from registers ----
        #pragma unroll
        for (int nt = 0; nt < 8; nt++) {
            uint32_t vb[8];
            uint32_t base = VdU + (uint32_t)(nt * 8 * A_ROWB) + laneKB;
            ldsm_x4(vb[0], vb[1], vb[2], vb[3], base);
            ldsm_x4(vb[4], vb[5], vb[6], vb[7], base + 64);
            #pragma unroll
            for (int ks = 0; ks < 4; ks++) {
                mma_f16(oacc[0][nt][0], oacc[0][nt][1], oacc[0][nt][2], oacc[0][nt][3],
                        sA2[0][2 * ks], sB2[0][2 * ks],
                        sA2[0][2 * ks + 1], sB2[0][2 * ks + 1],
                        vb[2 * ks], vb[2 * ks + 1]);
                mma_f16(oacc[1][nt][0], oacc[1][nt][1], oacc[1][nt][2], oacc[1][nt][3],
                        sA2[1][2 * ks], sB2[1][2 * ks],
                        sA2[1][2 * ks + 1], sB2[1][2 * ks + 1],
                        vb[2 * ks], vb[2 * ks + 1]);
            }
        }
        __syncthreads();
        buf ^= 1;
    }

    // ---- epilogue: normalize + fp16 store ----
    #pragma unroll
    for (int mt = 0; mt < 2; mt++) {
        const float invA = 1.0f / lA[mt], invB = 1.0f / lB[mt];
        const int row0 = q0 + wid * 32 + mt * 16 + gi;
        __half* Ob = Out + ((size_t)(bb * SEQ + row0)) * EMBED + h * HDIM;
        #pragma unroll
        for (int nt = 0; nt < 8; nt++) {
            int col = nt * 8 + 2 * ti;
            *(__half2*)(Ob + col) = __float22half2_rn(
                make_float2(oacc[mt][nt][0] * invA, oacc[mt][nt][1] * invA));
            *(__half2*)(Ob + (size_t)8 * EMBED + col) = __float22half2_rn(
                make_float2(oacc[mt][nt][2] * invB, oacc[mt][nt][3] * invB));
        }
    }
}

// ---------------- launch ----------------------------------------------------
extern "C" void kernel_launch(void* const* d_in, const int* in_sizes, int n_in,
                              void* d_out, int out_size)
{
    const float* q  = (const float*)d_in[0];
    const float* k  = (const float*)d_in[1];
    const float* v  = (const float*)d_in[2];
    const float* Wq = (const float*)d_in[3];
    const float* bq = (const float*)d_in[4];
    const float* Wk = (const float*)d_in[5];
    const float* bk = (const float*)d_in[6];
    const float* Wv = (const float*)d_in[7];
    const float* bv = (const float*)d_in[8];
    const float* Wo = (const float*)d_in[9];
    const float* bo = (const float*)d_in[10];
    float* out = (float*)d_out;

    __half *qh, *kh, *vh, *Wqt, *Wkt, *Wvt, *Wot, *Qp, *Kp, *Vt, *Ah;
    cudaGetSymbolAddress((void**)&qh,  g_qh);
    cudaGetSymbolAddress((void**)&kh,  g_kh);
    cudaGetSymbolAddress((void**)&vh,  g_vh);
    cudaGetSymbolAddress((void**)&Wqt, g_Wqt);
    cudaGetSymbolAddress((void**)&Wkt, g_Wkt);
    cudaGetSymbolAddress((void**)&Wvt, g_Wvt);
    cudaGetSymbolAddress((void**)&Wot, g_Wot);
    cudaGetSymbolAddress((void**)&Qp,  g_Qp);
    cudaGetSymbolAddress((void**)&Kp,  g_Kp);
    cudaGetSymbolAddress((void**)&Vt,  g_Vt);
    cudaGetSymbolAddress((void**)&Ah,  g_Ah);

    cudaFuncSetAttribute(attn_f16_kernel,
                         cudaFuncAttributeMaxDynamicSharedMemorySize,
                         ATTN_SMEM_BYTES);

    // unified pre-pass: y=0..2 cvt q/k/v, y=3 transpose+cvt the 4 weights
    dim3 pgrid(MROWS * EMBED / 4 / 256, 4);   // (4096, 4)
    prep_kernel<<<pgrid, 256>>>((const float4*)q, (const float4*)k, (const float4*)v,
                                (__half2*)qh, (__half2*)kh, (__half2*)vh,
                                Wq, Wk, Wv, Wo, Wqt, Wkt, Wvt, Wot);

    const float qscale = 0.125f * 1.4426950408889634f;   // 1/sqrt(64) * log2(e)
    GemmJob jq = { qh, Wqt, bq, (void*)Qp, qscale, 1 };
    GemmJob jk = { kh, Wkt, bk, (void*)Kp, 1.0f,   1 };
    GemmJob jv = { vh, Wvt, bv, (void*)Vt, 1.0f,   2 };
    GemmJob jo = { Ah, Wot, bo, (void*)out, 1.0f,  0 };

    dim3 qkv_grid(EMBED / 128, MROWS / 128, 3);   // (8, 32, 3) fused
    gemm_f16j<<<qkv_grid, 128>>>(jq, jk, jv);

    dim3 attn_grid(SEQ / 128, HEADS, BATCH);      // (16, 16, 2)
    attn_f16_kernel<<<attn_grid, 128, ATTN_SMEM_BYTES>>>(Qp, Kp, Vt, Ah);

    dim3 out_grid(EMBED / 128, MROWS / 128, 1);
    gemm_f16j<<<out_grid, 128>>>(jo, jo, jo);
}